// round 12
// baseline (speedup 1.0000x reference)
#include <cuda_runtime.h>
#include <cuda_bf16.h>
#include <math.h>
#include <stdint.h>

#define N_   4096
#define SEQ_ 41
#define VEC_ 15
#define T_   8
#define EMB_ 32
#define LDIM_ 256
#define RED_ 64
#define M1_  (N_ * SEQ_)   // 167936 rows = 1312 tiles of 128

// ---------------- scratch (device globals; no allocation) ----------------
__device__ float g_h[N_ * EMB_];
__device__ float g_emb[N_ * EMB_];
__device__ float g_sqn[N_];
__device__ float g_mu[EMB_];
__device__ float g_rstd[EMB_];
__device__ float g_psum[1024];
__device__ float g_pmin[1024];
__device__ float g_pmax[1024];
__device__ float g_dc[3];
__device__ float g_posvec[N_ * RED_];
__device__ float g_negvec[N_ * RED_];
__device__ float g_psn[N_];
__device__ float g_nsn[N_];
__device__ float g_sp[1024];
__device__ float g_sn[1024];
__device__ float g_TA[(size_t)M1_ * 64];
__device__ float g_T2[(size_t)M1_ * 128];
__device__ float g_Draw[(size_t)N_ * N_];
// bf16-split intermediates
__device__ __nv_bfloat16 g_Hh[(size_t)M1_ * 128];
__device__ __nv_bfloat16 g_Hl[(size_t)M1_ * 128];
__device__ __nv_bfloat16 g_W1Th[3 * 64 * 256];
__device__ __nv_bfloat16 g_W1Tl[3 * 64 * 256];
__device__ __nv_bfloat16 g_W2Th[2 * 64 * 64];
__device__ __nv_bfloat16 g_W2Tl[2 * 64 * 64];
__device__ __nv_bfloat16 g_pvh[N_ * 64], g_pvl[N_ * 64];
__device__ __nv_bfloat16 g_nvh[N_ * 64], g_nvl[N_ * 64];

__device__ __forceinline__ float fast_tanh(float x) {
    float e = __expf(2.0f * x);
    return 1.0f - 2.0f / (e + 1.0f);
}
__device__ __forceinline__ void bf16split(float x, __nv_bfloat16& h, __nv_bfloat16& l) {
    h = __float2bfloat16(x);
    l = __float2bfloat16(x - __bfloat162float(h));
}
__device__ __forceinline__ unsigned packbf2(__nv_bfloat16 a, __nv_bfloat16 b) {
    __nv_bfloat162 t = __nv_bfloat162(a, b);
    return *reinterpret_cast<unsigned*>(&t);
}
__device__ __forceinline__ uint32_t smem_u32(const void* p) {
    uint32_t a;
    asm("{ .reg .u64 t; cvta.to.shared.u64 t, %1; cvt.u32.u64 %0, t; }" : "=r"(a) : "l"(p));
    return a;
}

// bf16 warp MMA: D(16x8,f32) += A(16x16,row) * B(16x8,col)
__device__ __forceinline__ void mma_bf16(float c[4], const uint32_t a[4],
                                         uint32_t b0, uint32_t b1) {
    asm volatile(
        "mma.sync.aligned.m16n8k16.row.col.f32.bf16.bf16.f32 "
        "{%0,%1,%2,%3}, {%4,%5,%6,%7}, {%8,%9}, {%0,%1,%2,%3};"
        : "+f"(c[0]), "+f"(c[1]), "+f"(c[2]), "+f"(c[3])
        : "r"(a[0]), "r"(a[1]), "r"(a[2]), "r"(a[3]), "r"(b0), "r"(b1));
}
__device__ __forceinline__ void ldmx4(uint32_t r[4], uint32_t a) {
    asm volatile("ldmatrix.sync.aligned.m8n8.x4.shared.b16 {%0,%1,%2,%3}, [%4];"
        : "=r"(r[0]), "=r"(r[1]), "=r"(r[2]), "=r"(r[3]) : "r"(a));
}
__device__ __forceinline__ uint32_t ldm_addr(uint32_t base, int lane, int row0,
                                             int k0, int strideElem) {
    int row = row0 + (lane & 7) + ((lane >> 3) & 1) * 8;
    int col = k0 + (lane >> 4) * 8;
    return base + (uint32_t)(row * strideElem + col) * 2u;
}

// ---------------- K1: gather + interp + h = tanh(flat@W1 + b1) ----------------
__global__ void k_gather_h(const float* __restrict__ A, const int* __restrict__ C,
                           const float* __restrict__ W1, const float* __restrict__ b1) {
    __shared__ float flat[120];
    int n = blockIdx.x;
    int t = threadIdx.x;
    int start = C[2 * n], end = C[2 * n + 1];
    int len = end - start + 1;
    if (t < 120) {
        int j = t / VEC_, v = t % VEC_;
        float scale = (float)len / (float)T_;
        float src = fmaxf(scale * ((float)j + 0.5f) - 0.5f, 0.0f);
        int i0 = min((int)floorf(src), len - 1);
        int i1 = min(i0 + 1, len - 1);
        float w = src - (float)i0;
        const float* Ar = A + (size_t)n * SEQ_ * VEC_;
        float g0 = Ar[(start + i0) * VEC_ + v];
        float g1 = Ar[(start + i1) * VEC_ + v];
        flat[t] = (1.0f - w) * g0 + w * g1;
    }
    __syncthreads();
    if (t < 32) {
        float acc = b1[t];
#pragma unroll
        for (int k = 0; k < 120; k++) acc += flat[k] * W1[k * 32 + t];
        g_h[n * 32 + t] = tanhf(acc);
    }
}

// ---------------- K2: batchnorm stats ----------------
__global__ void k_bnstats() {
    __shared__ float ssum[32][33];
    __shared__ float ssq[32][33];
    int c = threadIdx.x & 31, g = threadIdx.x >> 5;
    float s = 0.f, q = 0.f;
    for (int n = g; n < N_; n += 32) {
        float v = g_h[n * 32 + c];
        s += v; q += v * v;
    }
    ssum[g][c] = s; ssq[g][c] = q;
    __syncthreads();
    if (threadIdx.x < 32) {
        float S = 0.f, Q = 0.f;
        for (int gg = 0; gg < 32; gg++) { S += ssum[gg][threadIdx.x]; Q += ssq[gg][threadIdx.x]; }
        float mu = S / (float)N_;
        float var = Q / (float)N_ - mu * mu;
        g_mu[threadIdx.x] = mu;
        g_rstd[threadIdx.x] = rsqrtf(var + 1e-5f);
    }
}

// ---------------- K3: emb + row sq-norms ----------------
__global__ void k_emb(const float* __restrict__ gamma, const float* __restrict__ beta) {
    int idx = blockIdx.x * 256 + threadIdx.x;
    int c = idx & 31;
    float e = gamma[c] * (g_h[idx] - g_mu[c]) * g_rstd[c] + beta[c];
    g_emb[idx] = e;
    float sq = e * e;
#pragma unroll
    for (int o = 16; o; o >>= 1) sq += __shfl_xor_sync(0xffffffffu, sq, o);
    if (c == 0) g_sqn[idx >> 5] = sq;
}

// ---------------- D tile GEMM helper (fp32 SIMT — precision-critical) ----------------
__device__ __forceinline__ void d_tile_gemm(int bi, int bj, int t,
                                            float sI[128][33], float sJ[128][33],
                                            float snI[128], float snJ[128],
                                            float acc[8][8]) {
    for (int i = t; i < 128 * 32; i += 256) {
        int r = i >> 5, k = i & 31;
        sI[r][k] = g_emb[(bi * 128 + r) * 32 + k];
        sJ[r][k] = g_emb[(bj * 128 + r) * 32 + k];
    }
    if (t < 128) snI[t] = g_sqn[bi * 128 + t];
    else snJ[t - 128] = g_sqn[bj * 128 + (t - 128)];
    __syncthreads();
    int tx = t & 15, ty = t >> 4;
#pragma unroll
    for (int k = 0; k < 32; k++) {
        float a[8], b[8];
#pragma unroll
        for (int r = 0; r < 8; r++) a[r] = sI[ty + 16 * r][k];
#pragma unroll
        for (int c = 0; c < 8; c++) b[c] = sJ[tx + 16 * c][k];
#pragma unroll
        for (int r = 0; r < 8; r++)
#pragma unroll
            for (int c = 0; c < 8; c++) acc[r][c] += a[r] * b[c];
    }
}

__global__ void k_dstats(const float* __restrict__ sigma_p) {
    __shared__ float sI[128][33], sJ[128][33];
    __shared__ float snI[128], snJ[128];
    __shared__ float rs[256], rmn[256], rmx[256];
    int bi = blockIdx.y, bj = blockIdx.x, t = threadIdx.x;
    float acc[8][8];
#pragma unroll
    for (int r = 0; r < 8; r++)
#pragma unroll
        for (int c = 0; c < 8; c++) acc[r][c] = 0.f;
    d_tile_gemm(bi, bj, t, sI, sJ, snI, snJ, acc);
    float inv2s;
    { float sg = sigma_p[0]; inv2s = 0.5f / (sg * sg); }
    int tx = t & 15, ty = t >> 4;
    float lsum = 0.f, lmin = 3.4e38f, lmax = -3.4e38f;
#pragma unroll
    for (int r = 0; r < 8; r++) {
        int gi = bi * 128 + ty + 16 * r;
#pragma unroll
        for (int c = 0; c < 8; c++) {
            int gj = bj * 128 + tx + 16 * c;
            float sq = snI[ty + 16 * r] + snJ[tx + 16 * c] - 2.0f * acc[r][c];
            sq = fmaxf(sq, 0.0f);
            float d = (sq > 0.0f) ? sqrtf(sq) : 0.0f;
            float val = __expf(-d * inv2s);
            g_Draw[(size_t)gi * N_ + gj] = val;
            if (gi != gj) { lsum += val; lmin = fminf(lmin, val); lmax = fmaxf(lmax, val); }
        }
    }
    rs[t] = lsum; rmn[t] = lmin; rmx[t] = lmax;
    __syncthreads();
    for (int o = 128; o; o >>= 1) {
        if (t < o) {
            rs[t] += rs[t + o];
            rmn[t] = fminf(rmn[t], rmn[t + o]);
            rmx[t] = fmaxf(rmx[t], rmx[t + o]);
        }
        __syncthreads();
    }
    if (t == 0) {
        int bid = bi * 32 + bj;
        g_psum[bid] = rs[0]; g_pmin[bid] = rmn[0]; g_pmax[bid] = rmx[0];
    }
}

__global__ void k_dconsts() {
    __shared__ float rs[1024], rmn[1024], rmx[1024];
    int t = threadIdx.x;
    rs[t] = g_psum[t]; rmn[t] = g_pmin[t]; rmx[t] = g_pmax[t];
    __syncthreads();
    for (int o = 512; o; o >>= 1) {
        if (t < o) {
            rs[t] += rs[t + o];
            rmn[t] = fminf(rmn[t], rmn[t + o]);
            rmx[t] = fmaxf(rmx[t], rmx[t + o]);
        }
        __syncthreads();
    }
    if (t == 0) {
        float avg = rs[0] / ((float)N_ * (float)(N_ - 1));
        float mn = (rmn[0] < avg) ? 0.0f : rmn[0];
        float mx = rmx[0];
        if (mx == mn) mx = mn + 1.0f;
        g_dc[0] = avg; g_dc[1] = mn; g_dc[2] = 1.0f / (mx - mn);
    }
}

// D finalize: output pointer only 4B-aligned -> scalar stores
__global__ void k_dfinal(float* __restrict__ D) {
    float avg = g_dc[0], mn = g_dc[1], inv = g_dc[2];
    size_t base = ((size_t)blockIdx.x * 256 + threadIdx.x) * 4;
    float4 v = *(const float4*)(g_Draw + base);
    float vv[4] = { v.x, v.y, v.z, v.w };
#pragma unroll
    for (int j = 0; j < 4; j++) {
        size_t idx = base + j;
        int gi = (int)(idx >> 12);
        int gj = (int)(idx & 4095);
        float dt = (vv[j] < avg) ? 0.0f : vv[j];
        D[idx] = (gi == gj) ? 1.0f : (dt - mn) * inv;
    }
}

// ---------------- W split/transpose precompute ----------------
__global__ void k_wsplit(const float* __restrict__ Wp1, const float* __restrict__ Wq1,
                         const float* __restrict__ Wa,
                         const float* __restrict__ Wp2, const float* __restrict__ Wq2) {
    int idx = blockIdx.x * 256 + threadIdx.x;
    if (idx < 3 * 64 * 256) {
        int w = idx >> 14;
        int n = (idx >> 8) & 63;
        int k = idx & 255;
        const float* W = (w == 0) ? Wp1 : (w == 1) ? Wq1 : Wa;
        float x = W[k * 64 + n];
        __nv_bfloat16 h, l; bf16split(x, h, l);
        g_W1Th[idx] = h; g_W1Tl[idx] = l;
    }
    if (idx < 2 * 64 * 64) {
        int p = idx >> 12;
        int n = (idx >> 6) & 63;
        int k = idx & 63;
        const float* W = p ? Wq2 : Wp2;
        float x = W[k * 64 + n];
        __nv_bfloat16 h, l; bf16split(x, h, l);
        g_W2Th[idx] = h; g_W2Tl[idx] = l;
    }
}

// ---------------- GEMM1 (mma.sync bf16 + ldmatrix) ----------------
#define G1_A_ELEM (128 * 72)
#define G1_B_ELEM (192 * 72)
#define G1_SMEM ((2 * G1_A_ELEM + 2 * G1_B_ELEM) * 2)

__global__ void __launch_bounds__(512)
k_gemm1_mma(const float* __restrict__ L, const float* __restrict__ Pw,
            const float* __restrict__ Nw, const int* __restrict__ C,
            const float* __restrict__ bp1, const float* __restrict__ bq1,
            const float* __restrict__ ba) {
    extern __shared__ __nv_bfloat16 sm1[];
    __nv_bfloat16* sAh = sm1;
    __nv_bfloat16* sAl = sAh + G1_A_ELEM;
    __nv_bfloat16* sBh = sAl + G1_A_ELEM;
    __nv_bfloat16* sBl = sBh + G1_B_ELEM;
    __shared__ float sMp[128], sMn[128], sBias[192];

    int t = threadIdx.x;
    int m0 = blockIdx.x * 128;
    int wid = t >> 5, lane = t & 31;
    int wr = wid >> 2, wc = wid & 3;
    int g = lane >> 2, t4 = lane & 3;

    if (t < 128) {
        int m = m0 + t;
        int n = m / SEQ_, s = m - n * SEQ_;
        int st = C[2 * n], en = C[2 * n + 1];
        bool in = (s >= st && s <= en);
        sMp[t] = in ? Pw[n * SEQ_ + s] : 0.0f;
        sMn[t] = in ? 0.0f : Nw[n * SEQ_ + s];
    } else if (t < 320) {
        int c = t - 128;
        sBias[c] = (c < 64) ? bp1[c] : (c < 128) ? bq1[c - 64] : ba[c - 128];
    }

    uint32_t aAh = smem_u32(sAh), aAl = smem_u32(sAl);
    uint32_t aBh = smem_u32(sBh), aBl = smem_u32(sBl);

    float acc[2][6][4];
#pragma unroll
    for (int r = 0; r < 2; r++)
#pragma unroll
        for (int c = 0; c < 6; c++)
#pragma unroll
            for (int j = 0; j < 4; j++) acc[r][c][j] = 0.f;

    for (int kc = 0; kc < 4; kc++) {
        __syncthreads();
        for (int i = t; i < 2048; i += 512) {
            int r = i >> 4, k4 = (i & 15) * 4;
            float4 v = *(const float4*)(L + (size_t)(m0 + r) * 256 + kc * 64 + k4);
            float xs[4] = { v.x, v.y, v.z, v.w };
            __nv_bfloat16 h[4], l[4];
#pragma unroll
            for (int j = 0; j < 4; j++) bf16split(xs[j], h[j], l[j]);
            uint2 uh = { packbf2(h[0], h[1]), packbf2(h[2], h[3]) };
            uint2 ul = { packbf2(l[0], l[1]), packbf2(l[2], l[3]) };
            *(uint2*)(sAh + r * 72 + k4) = uh;
            *(uint2*)(sAl + r * 72 + k4) = ul;
        }
        for (int i = t; i < 1536; i += 512) {
            int n = i >> 3, k8 = (i & 7) * 8;
            size_t goff = (size_t)(n >> 6) * 16384 + (size_t)(n & 63) * 256 + kc * 64 + k8;
            *(uint4*)(sBh + n * 72 + k8) = *(const uint4*)(g_W1Th + goff);
            *(uint4*)(sBl + n * 72 + k8) = *(const uint4*)(g_W1Tl + goff);
        }
        __syncthreads();

#pragma unroll
        for (int pass = 0; pass < 3; pass++) {
            uint32_t A = (pass == 2) ? aAl : aAh;
            uint32_t B = (pass == 1) ? aBl : aBh;
#pragma unroll
            for (int ks = 0; ks < 4; ks++) {
                int k0 = ks * 16;
                uint32_t af[2][4];
                ldmx4(af[0], ldm_addr(A, lane, wr * 32, k0, 72));
                ldmx4(af[1], ldm_addr(A, lane, wr * 32 + 16, k0, 72));
#pragma unroll
                for (int cp = 0; cp < 3; cp++) {
                    uint32_t bf[4];
                    ldmx4(bf, ldm_addr(B, lane, wc * 48 + cp * 16, k0, 72));
                    mma_bf16(acc[0][2 * cp],     af[0], bf[0], bf[2]);
                    mma_bf16(acc[0][2 * cp + 1], af[0], bf[1], bf[3]);
                    mma_bf16(acc[1][2 * cp],     af[1], bf[0], bf[2]);
                    mma_bf16(acc[1][2 * cp + 1], af[1], bf[1], bf[3]);
                }
            }
        }
    }

#pragma unroll
    for (int rt = 0; rt < 2; rt++) {
        int r0 = wr * 32 + rt * 16 + g;
        int r1 = r0 + 8;
        size_t m0r0 = (size_t)(m0 + r0);
        size_t m0r1 = (size_t)(m0 + r1);
        float mp0 = sMp[r0], mn0 = sMn[r0];
        float mp1 = sMp[r1], mn1 = sMn[r1];
#pragma unroll
        for (int ct = 0; ct < 6; ct++) {
            int nn = wc * 48 + ct * 8 + 2 * t4;
            float b0 = sBias[nn], b1 = sBias[nn + 1];
            if (nn < 128) {
                float s0 = (nn < 64) ? mp0 : mn0;
                float s1 = (nn < 64) ? mp1 : mn1;
                float h00 = fast_tanh(s0 * acc[rt][ct][0] + b0);
                float h01 = fast_tanh(s0 * acc[rt][ct][1] + b1);
                float h10 = fast_tanh(s1 * acc[rt][ct][2] + b0);
                float h11 = fast_tanh(s1 * acc[rt][ct][3] + b1);
                __nv_bfloat16 hh, hl, h2h, h2l;
                bf16split(h00, hh, hl); bf16split(h01, h2h, h2l);
                *(unsigned*)(&g_Hh[m0r0 * 128 + nn]) = packbf2(hh, h2h);
                *(unsigned*)(&g_Hl[m0r0 * 128 + nn]) = packbf2(hl, h2l);
                bf16split(h10, hh, hl); bf16split(h11, h2h, h2l);
                *(unsigned*)(&g_Hh[m0r1 * 128 + nn]) = packbf2(hh, h2h);
                *(unsigned*)(&g_Hl[m0r1 * 128 + nn]) = packbf2(hl, h2l);
            } else {
                int na = nn - 128;
                float s0 = mp0 + mn0, s1 = mp1 + mn1;
                float2 o0, o1;
                o0.x = fast_tanh(s0 * acc[rt][ct][0] + b0);
                o0.y = fast_tanh(s0 * acc[rt][ct][1] + b1);
                o1.x = fast_tanh(s1 * acc[rt][ct][2] + b0);
                o1.y = fast_tanh(s1 * acc[rt][ct][3] + b1);
                *(float2*)(g_TA + m0r0 * 64 + na) = o0;
                *(float2*)(g_TA + m0r1 * 64 + na) = o1;
            }
        }
    }
}

// ---------------- GEMM2 (mma.sync bf16 + ldmatrix) ----------------
#define G2_H_ELEM (128 * 136)
#define G2_W_ELEM (2 * 64 * 72)
#define G2_SMEM ((2 * G2_H_ELEM + 2 * G2_W_ELEM) * 2)

__global__ void __launch_bounds__(512)
k_gemm2_mma(const float* __restrict__ bp2, const float* __restrict__ bq2) {
    extern __shared__ __nv_bfloat16 sm2[];
    __nv_bfloat16* sHh = sm2;
    __nv_bfloat16* sHl = sHh + G2_H_ELEM;
    __nv_bfloat16* sWh = sHl + G2_H_ELEM;
    __nv_bfloat16* sWl = sWh + G2_W_ELEM;
    __shared__ float sBias[128];

    int t = threadIdx.x;
    int m0 = blockIdx.x * 128;
    int wid = t >> 5, lane = t & 31;
    int wr = wid >> 2, wc = wid & 3;
    int g = lane >> 2, t4 = lane & 3;
    int region = wc >> 1;
    int kbase = region * 64;

    if (t < 128) sBias[t] = (t < 64) ? bp2[t] : bq2[t - 64];

    for (int i = t; i < 2048; i += 512) {
        int r = i >> 4, k8 = (i & 15) * 8;
        size_t goff = (size_t)(m0 + r) * 128 + k8;
        *(uint4*)(sHh + r * 136 + k8) = *(const uint4*)(g_Hh + goff);
        *(uint4*)(sHl + r * 136 + k8) = *(const uint4*)(g_Hl + goff);
    }
    for (int i = t; i < 1024; i += 512) {
        int rg = i >> 9, n = (i >> 3) & 63, k8 = (i & 7) * 8;
        size_t goff = (size_t)rg * 4096 + (size_t)n * 64 + k8;
        *(uint4*)(sWh + (rg * 64 + n) * 72 + k8) = *(const uint4*)(g_W2Th + goff);
        *(uint4*)(sWl + (rg * 64 + n) * 72 + k8) = *(const uint4*)(g_W2Tl + goff);
    }
    __syncthreads();

    uint32_t aHh = smem_u32(sHh), aHl = smem_u32(sHl);
    uint32_t aWh = smem_u32(sWh), aWl = smem_u32(sWl);

    float acc[2][4][4];
#pragma unroll
    for (int r = 0; r < 2; r++)
#pragma unroll
        for (int c = 0; c < 4; c++)
#pragma unroll
            for (int j = 0; j < 4; j++) acc[r][c][j] = 0.f;

#pragma unroll
    for (int pass = 0; pass < 3; pass++) {
        uint32_t A = (pass == 2) ? aHl : aHh;
        uint32_t B = (pass == 1) ? aWl : aWh;
#pragma unroll
        for (int ks = 0; ks < 4; ks++) {
            int k0 = kbase + ks * 16;
            int kl = ks * 16;
            uint32_t af[2][4];
            ldmx4(af[0], ldm_addr(A, lane, wr * 32, k0, 136));
            ldmx4(af[1], ldm_addr(A, lane, wr * 32 + 16, k0, 136));
#pragma unroll
            for (int cp = 0; cp < 2; cp++) {
                uint32_t bf[4];
                ldmx4(bf, ldm_addr(B, lane, region * 64 + (wc & 1) * 32 + cp * 16, kl, 72));
                mma_bf16(acc[0][2 * cp],     af[0], bf[0], bf[2]);
                mma_bf16(acc[0][2 * cp + 1], af[0], bf[1], bf[3]);
                mma_bf16(acc[1][2 * cp],     af[1], bf[0], bf[2]);
                mma_bf16(acc[1][2 * cp + 1], af[1], bf[1], bf[3]);
            }
        }
    }

#pragma unroll
    for (int rt = 0; rt < 2; rt++) {
        int r0 = wr * 32 + rt * 16 + g;
        int r1 = r0 + 8;
        size_t m0r0 = (size_t)(m0 + r0);
        size_t m0r1 = (size_t)(m0 + r1);
#pragma unroll
        for (int ct = 0; ct < 4; ct++) {
            int nn = wc * 32 + ct * 8 + 2 * t4;
            float b0 = sBias[nn], b1 = sBias[nn + 1];
            float2 o0, o1;
            o0.x = fast_tanh(acc[rt][ct][0] + b0);
            o0.y = fast_tanh(acc[rt][ct][1] + b1);
            o1.x = fast_tanh(acc[rt][ct][2] + b0);
            o1.y = fast_tanh(acc[rt][ct][3] + b1);
            *(float2*)(g_T2 + m0r0 * 128 + nn) = o0;
            *(float2*)(g_T2 + m0r1 * 128 + nn) = o1;
        }
    }
}

// ---------------- R1: final_feature mean ----------------
__global__ void k_r1(float* __restrict__ out_ff) {
    int n = blockIdx.x, t = threadIdx.x;   // 64 threads
    float s = 0.f;
#pragma unroll 8
    for (int q = 0; q < SEQ_; q++) s += g_TA[((size_t)n * SEQ_ + q) * 64 + t];
    out_ff[n * 64 + t] = s * (1.0f / (float)SEQ_);
}

// ---------------- R2: pos/neg vec means + sq-norms + bf16 split ----------------
__global__ void k_r2() {
    __shared__ float ws[4];
    int n = blockIdx.x, t = threadIdx.x;   // 128 threads
    float s = 0.f;
#pragma unroll 8
    for (int q = 0; q < SEQ_; q++) s += g_T2[((size_t)n * SEQ_ + q) * 128 + t];
    float v = s * (1.0f / (float)SEQ_);
    __nv_bfloat16 h, l; bf16split(v, h, l);
    if (t < 64) {
        g_posvec[n * 64 + t] = v;
        g_pvh[n * 64 + t] = h; g_pvl[n * 64 + t] = l;
    } else {
        g_negvec[n * 64 + (t - 64)] = v;
        g_nvh[n * 64 + (t - 64)] = h; g_nvl[n * 64 + (t - 64)] = l;
    }
    float sq = v * v;
#pragma unroll
    for (int o = 16; o; o >>= 1) sq += __shfl_xor_sync(0xffffffffu, sq, o);
    if ((t & 31) == 0) ws[t >> 5] = sq;
    __syncthreads();
    if (t == 0) {
        g_psn[n] = ws[0] + ws[1];
        g_nsn[n] = ws[2] + ws[3];
    }
}

// ---------------- K8: similarity sums (tensor-core) ----------------
#define SIM_STR 72
#define SIM_TILE (128 * SIM_STR)
#define SIMTC_SMEM (6 * SIM_TILE * 2)   // 110592 bytes
__global__ void __launch_bounds__(256)
k_sims_tc() {
    extern __shared__ __nv_bfloat16 ssm[];
    __nv_bfloat16* pIh = ssm;
    __nv_bfloat16* pIl = pIh + SIM_TILE;
    __nv_bfloat16* pJh = pIl + SIM_TILE;
    __nv_bfloat16* pJl = pJh + SIM_TILE;
    __nv_bfloat16* nJh = pJl + SIM_TILE;
    __nv_bfloat16* nJl = nJh + SIM_TILE;
    __shared__ float snI[128], snP[128], snN[128];
    __shared__ float rp[256], rn[256];

    int bi = blockIdx.y, bj = blockIdx.x, t = threadIdx.x;
    int wid = t >> 5, lane = t & 31;
    int wr = wid >> 1, wc = wid & 1;
    int g = lane >> 2, t4 = lane & 3;

    for (int i = t; i < 1024; i += 256) {
        int r = i >> 3, q = (i & 7) * 8;
        *(uint4*)(pIh + r * SIM_STR + q) = *(const uint4*)(g_pvh + (bi * 128 + r) * 64 + q);
        *(uint4*)(pIl + r * SIM_STR + q) = *(const uint4*)(g_pvl + (bi * 128 + r) * 64 + q);
        *(uint4*)(pJh + r * SIM_STR + q) = *(const uint4*)(g_pvh + (bj * 128 + r) * 64 + q);
        *(uint4*)(pJl + r * SIM_STR + q) = *(const uint4*)(g_pvl + (bj * 128 + r) * 64 + q);
        *(uint4*)(nJh + r * SIM_STR + q) = *(const uint4*)(g_nvh + (bj * 128 + r) * 64 + q);
        *(uint4*)(nJl + r * SIM_STR + q) = *(const uint4*)(g_nvl + (bj * 128 + r) * 64 + q);
    }
    if (t < 128) { snI[t] = g_psn[bi * 128 + t]; snN[t] = g_nsn[bj * 128 + t]; }
    else snP[t - 128] = g_psn[bj * 128 + (t - 128)];
    __syncthreads();

    uint32_t aIh = smem_u32(pIh), aIl = smem_u32(pIl);
    uint32_t aPh = smem_u32(pJh), aPl = smem_u32(pJl);
    uint32_t aNh = smem_u32(nJh), aNl = smem_u32(nJl);

    float lp = 0.f, ln = 0.f;
#pragma unroll
    for (int targ = 0; targ < 2; targ++) {
        uint32_t bh = targ ? aNh : aPh;
        uint32_t bl = targ ? aNl : aPl;
        float acc[2][8][4];
#pragma unroll
        for (int r = 0; r < 2; r++)
#pragma unroll
            for (int c = 0; c < 8; c++)
#pragma unroll
                for (int j = 0; j < 4; j++) acc[r][c][j] = 0.f;

#pragma unroll
        for (int pass = 0; pass < 3; pass++) {
            uint32_t A = (pass == 2) ? aIl : aIh;
            uint32_t B = (pass == 1) ? bl : bh;
#pragma unroll
            for (int ks = 0; ks < 4; ks++) {
                int k0 = ks * 16;
                uint32_t af[2][4];
                ldmx4(af[0], ldm_addr(A, lane, wr * 32, k0, SIM_STR));
                ldmx4(af[1], ldm_addr(A, lane, wr * 32 + 16, k0, SIM_STR));
#pragma unroll
                for (int cp = 0; cp < 4; cp++) {
                    uint32_t bf[4];
                    ldmx4(bf, ldm_addr(B, lane, wc * 64 + cp * 16, k0, SIM_STR));
                    mma_bf16(acc[0][2 * cp],     af[0], bf[0], bf[2]);
                    mma_bf16(acc[0][2 * cp + 1], af[0], bf[1], bf[3]);
                    mma_bf16(acc[1][2 * cp],     af[1], bf[0], bf[2]);
                    mma_bf16(acc[1][2 * cp + 1], af[1], bf[1], bf[3]);
                }
            }
        }

        const float* snX = targ ? snN : snP;
        float tot = 0.f;
#pragma unroll
        for (int rt = 0; rt < 2; rt++) {
#pragma unroll
            for (int ct = 0; ct < 8; ct++) {
                int rl = wr * 32 + rt * 16 + g;
                int cl = wc * 64 + ct * 8 + 2 * t4;
                float nI0 = snI[rl], nI1 = snI[rl + 8];
                float c0 = snX[cl], c1 = snX[cl + 1];
                float sqv[4] = { nI0 + c0 - 2.f * acc[rt][ct][0],
                                 nI0 + c1 - 2.f * acc[rt][ct][1],
                                 nI1 + c0 - 2.f * acc[rt][ct][2],
                                 nI1 + c1 - 2.f * acc[rt][ct][3] };
#pragma unroll
                for (int j = 0; j < 4; j++) {
                    float sq = fmaxf(sqv[j], 0.0f);
                    float d = (sq > 0.0f) ? sqrtf(sq) : 0.0f;
                    tot += __expf(-d);
                }
            }
        }
        if (targ == 0) lp = tot; else ln = tot;
    }
    rp[t] = lp; rn[t] = ln;
    __syncthreads();
    for (int o = 128; o; o >>= 1) {
        if (t < o) { rp[t] += rp[t + o]; rn[t] += rn[t + o]; }
        __syncthreads();
    }
    if (t == 0) {
        int bid = bi * 32 + bj;
        g_sp[bid] = rp[0]; g_sn[bid] = rn[0];
    }
}

__global__ void k_loss(float* __restrict__ out_loss) {
    __shared__ float rp[1024], rn[1024];
    int t = threadIdx.x;
    rp[t] = g_sp[t]; rn[t] = g_sn[t];
    __syncthreads();
    for (int o = 512; o; o >>= 1) {
        if (t < o) { rp[t] += rp[t + o]; rn[t] += rn[t + o]; }
        __syncthreads();
    }
    if (t == 0) out_loss[0] = -logf(rp[0] / rn[0]);
}

// ---------------- launch ----------------
extern "C" void kernel_launch(void* const* d_in, const int* in_sizes, int n_in,
                              void* d_out, int out_size) {
    const float* A     = (const float*)d_in[0];
    const int*   C     = (const int*)d_in[1];
    const float* L     = (const float*)d_in[2];
    const float* W1    = (const float*)d_in[3];
    const float* b1    = (const float*)d_in[4];
    const float* gam   = (const float*)d_in[5];
    const float* bet   = (const float*)d_in[6];
    const float* sig   = (const float*)d_in[7];
    const float* Pw    = (const float*)d_in[8];
    const float* Nw    = (const float*)d_in[9];
    const float* Wp1   = (const float*)d_in[10];
    const float* bp1   = (const float*)d_in[11];
    const float* Wp2   = (const float*)d_in[12];
    const float* bp2   = (const float*)d_in[13];
    const float* Wq1   = (const float*)d_in[14];
    const float* bq1   = (const float*)d_in[15];
    const float* Wq2   = (const float*)d_in[16];
    const float* bq2   = (const float*)d_in[17];
    const float* Wa    = (const float*)d_in[18];
    const float* ba    = (const float*)d_in[19];

    float* out = (float*)d_out;
    float* out_ff   = out;                    // [4096*64]
    float* out_loss = out + N_ * RED_;        // [1]
    float* out_D    = out + N_ * RED_ + 1;    // [4096*4096], only 4B-aligned!

    cudaFuncSetAttribute(k_gemm1_mma, cudaFuncAttributeMaxDynamicSharedMemorySize, G1_SMEM);
    cudaFuncSetAttribute(k_gemm2_mma, cudaFuncAttributeMaxDynamicSharedMemorySize, G2_SMEM);
    cudaFuncSetAttribute(k_sims_tc, cudaFuncAttributeMaxDynamicSharedMemorySize, SIMTC_SMEM);

    k_wsplit<<<192, 256>>>(Wp1, Wq1, Wa, Wp2, Wq2);
    k_gather_h<<<N_, 128>>>(A, C, W1, b1);
    k_bnstats<<<1, 1024>>>();
    k_emb<<<512, 256>>>(gam, bet);
    k_dstats<<<dim3(32, 32), 256>>>(sig);
    k_dconsts<<<1, 1024>>>();
    k_dfinal<<<(N_ * (N_ / 4)) / 256, 256>>>(out_D);
    k_gemm1_mma<<<M1_ / 128, 512, G1_SMEM>>>(L, Pw, Nw, C, bp1, bq1, ba);
    k_gemm2_mma<<<M1_ / 128, 512, G2_SMEM>>>(bp2, bq2);
    k_r1<<<N_, 64>>>(out_ff);
    k_r2<<<N_, 128>>>();
    k_sims_tc<<<dim3(32, 32), 256, SIMTC_SMEM>>>();
    k_loss<<<1, 1024>>>(out_loss);
}

// round 13
// speedup vs baseline: 1.4929x; 1.4929x over previous
#include <cuda_runtime.h>
#include <cuda_bf16.h>
#include <math.h>
#include <stdint.h>

#define N_   4096
#define SEQ_ 41
#define VEC_ 15
#define T_   8
#define EMB_ 32
#define LDIM_ 256
#define RED_ 64
#define M1_  (N_ * SEQ_)   // 167936 rows = 1312 tiles of 128

// ---------------- scratch (device globals; no allocation) ----------------
__device__ float g_h[N_ * EMB_];
__device__ float g_emb[N_ * EMB_];
__device__ float g_sqn[N_];
__device__ float g_mu[EMB_];
__device__ float g_rstd[EMB_];
__device__ float g_psum[1024];
__device__ float g_pmin[1024];
__device__ float g_pmax[1024];
__device__ float g_dc[3];
__device__ float g_posvec[N_ * RED_];
__device__ float g_negvec[N_ * RED_];
__device__ float g_psn[N_];
__device__ float g_nsn[N_];
__device__ float g_sp[1024];
__device__ float g_sn[1024];
__device__ float g_TA[(size_t)M1_ * 64];
__device__ float g_T2[(size_t)M1_ * 128];
__device__ float g_Draw[(size_t)N_ * N_];
// bf16-split intermediates
__device__ __nv_bfloat16 g_Hh[(size_t)M1_ * 128];
__device__ __nv_bfloat16 g_Hl[(size_t)M1_ * 128];
__device__ __nv_bfloat16 g_W1Th[3 * 64 * 256];
__device__ __nv_bfloat16 g_W1Tl[3 * 64 * 256];
__device__ __nv_bfloat16 g_W2Th[2 * 64 * 64];
__device__ __nv_bfloat16 g_W2Tl[2 * 64 * 64];
__device__ __nv_bfloat16 g_pvh[N_ * 64], g_pvl[N_ * 64];
__device__ __nv_bfloat16 g_nvh[N_ * 64], g_nvl[N_ * 64];

__device__ __forceinline__ float fast_tanh(float x) {
    float e = __expf(2.0f * x);
    return 1.0f - 2.0f / (e + 1.0f);
}
__device__ __forceinline__ void bf16split(float x, __nv_bfloat16& h, __nv_bfloat16& l) {
    h = __float2bfloat16(x);
    l = __float2bfloat16(x - __bfloat162float(h));
}
__device__ __forceinline__ unsigned packbf2(__nv_bfloat16 a, __nv_bfloat16 b) {
    __nv_bfloat162 t = __nv_bfloat162(a, b);
    return *reinterpret_cast<unsigned*>(&t);
}

// bf16 warp MMA: D(16x8,f32) += A(16x16,row) * B(16x8,col)
__device__ __forceinline__ void mma_bf16(float c[4], const uint32_t a[4],
                                         uint32_t b0, uint32_t b1) {
    asm volatile(
        "mma.sync.aligned.m16n8k16.row.col.f32.bf16.bf16.f32 "
        "{%0,%1,%2,%3}, {%4,%5,%6,%7}, {%8,%9}, {%0,%1,%2,%3};"
        : "+f"(c[0]), "+f"(c[1]), "+f"(c[2]), "+f"(c[3])
        : "r"(a[0]), "r"(a[1]), "r"(a[2]), "r"(a[3]), "r"(b0), "r"(b1));
}

// ---------------- K1: gather + interp + h = tanh(flat@W1 + b1) ----------------
__global__ void k_gather_h(const float* __restrict__ A, const int* __restrict__ C,
                           const float* __restrict__ W1, const float* __restrict__ b1) {
    __shared__ float flat[120];
    int n = blockIdx.x;
    int t = threadIdx.x;
    int start = C[2 * n], end = C[2 * n + 1];
    int len = end - start + 1;
    if (t < 120) {
        int j = t / VEC_, v = t % VEC_;
        float scale = (float)len / (float)T_;
        float src = fmaxf(scale * ((float)j + 0.5f) - 0.5f, 0.0f);
        int i0 = min((int)floorf(src), len - 1);
        int i1 = min(i0 + 1, len - 1);
        float w = src - (float)i0;
        const float* Ar = A + (size_t)n * SEQ_ * VEC_;
        float g0 = Ar[(start + i0) * VEC_ + v];
        float g1 = Ar[(start + i1) * VEC_ + v];
        flat[t] = (1.0f - w) * g0 + w * g1;
    }
    __syncthreads();
    if (t < 32) {
        float acc = b1[t];
#pragma unroll
        for (int k = 0; k < 120; k++) acc += flat[k] * W1[k * 32 + t];
        g_h[n * 32 + t] = tanhf(acc);
    }
}

// ---------------- K2: batchnorm stats ----------------
__global__ void k_bnstats() {
    __shared__ float ssum[32][33];
    __shared__ float ssq[32][33];
    int c = threadIdx.x & 31, g = threadIdx.x >> 5;
    float s = 0.f, q = 0.f;
    for (int n = g; n < N_; n += 32) {
        float v = g_h[n * 32 + c];
        s += v; q += v * v;
    }
    ssum[g][c] = s; ssq[g][c] = q;
    __syncthreads();
    if (threadIdx.x < 32) {
        float S = 0.f, Q = 0.f;
        for (int gg = 0; gg < 32; gg++) { S += ssum[gg][threadIdx.x]; Q += ssq[gg][threadIdx.x]; }
        float mu = S / (float)N_;
        float var = Q / (float)N_ - mu * mu;
        g_mu[threadIdx.x] = mu;
        g_rstd[threadIdx.x] = rsqrtf(var + 1e-5f);
    }
}

// ---------------- K3: emb + row sq-norms ----------------
__global__ void k_emb(const float* __restrict__ gamma, const float* __restrict__ beta) {
    int idx = blockIdx.x * 256 + threadIdx.x;
    int c = idx & 31;
    float e = gamma[c] * (g_h[idx] - g_mu[c]) * g_rstd[c] + beta[c];
    g_emb[idx] = e;
    float sq = e * e;
#pragma unroll
    for (int o = 16; o; o >>= 1) sq += __shfl_xor_sync(0xffffffffu, sq, o);
    if (c == 0) g_sqn[idx >> 5] = sq;
}

// ---------------- D tile GEMM helper (fp32 SIMT — precision-critical) ----------------
__device__ __forceinline__ void d_tile_gemm(int bi, int bj, int t,
                                            float sI[128][33], float sJ[128][33],
                                            float snI[128], float snJ[128],
                                            float acc[8][8]) {
    for (int i = t; i < 128 * 32; i += 256) {
        int r = i >> 5, k = i & 31;
        sI[r][k] = g_emb[(bi * 128 + r) * 32 + k];
        sJ[r][k] = g_emb[(bj * 128 + r) * 32 + k];
    }
    if (t < 128) snI[t] = g_sqn[bi * 128 + t];
    else snJ[t - 128] = g_sqn[bj * 128 + (t - 128)];
    __syncthreads();
    int tx = t & 15, ty = t >> 4;
#pragma unroll
    for (int k = 0; k < 32; k++) {
        float a[8], b[8];
#pragma unroll
        for (int r = 0; r < 8; r++) a[r] = sI[ty + 16 * r][k];
#pragma unroll
        for (int c = 0; c < 8; c++) b[c] = sJ[tx + 16 * c][k];
#pragma unroll
        for (int r = 0; r < 8; r++)
#pragma unroll
            for (int c = 0; c < 8; c++) acc[r][c] += a[r] * b[c];
    }
}

__global__ void k_dstats(const float* __restrict__ sigma_p) {
    __shared__ float sI[128][33], sJ[128][33];
    __shared__ float snI[128], snJ[128];
    __shared__ float rs[256], rmn[256], rmx[256];
    int bi = blockIdx.y, bj = blockIdx.x, t = threadIdx.x;
    float acc[8][8];
#pragma unroll
    for (int r = 0; r < 8; r++)
#pragma unroll
        for (int c = 0; c < 8; c++) acc[r][c] = 0.f;
    d_tile_gemm(bi, bj, t, sI, sJ, snI, snJ, acc);
    float inv2s;
    { float sg = sigma_p[0]; inv2s = 0.5f / (sg * sg); }
    int tx = t & 15, ty = t >> 4;
    float lsum = 0.f, lmin = 3.4e38f, lmax = -3.4e38f;
#pragma unroll
    for (int r = 0; r < 8; r++) {
        int gi = bi * 128 + ty + 16 * r;
#pragma unroll
        for (int c = 0; c < 8; c++) {
            int gj = bj * 128 + tx + 16 * c;
            float sq = snI[ty + 16 * r] + snJ[tx + 16 * c] - 2.0f * acc[r][c];
            sq = fmaxf(sq, 0.0f);
            float d = (sq > 0.0f) ? sqrtf(sq) : 0.0f;
            float val = __expf(-d * inv2s);
            g_Draw[(size_t)gi * N_ + gj] = val;
            if (gi != gj) { lsum += val; lmin = fminf(lmin, val); lmax = fmaxf(lmax, val); }
        }
    }
    rs[t] = lsum; rmn[t] = lmin; rmx[t] = lmax;
    __syncthreads();
    for (int o = 128; o; o >>= 1) {
        if (t < o) {
            rs[t] += rs[t + o];
            rmn[t] = fminf(rmn[t], rmn[t + o]);
            rmx[t] = fmaxf(rmx[t], rmx[t + o]);
        }
        __syncthreads();
    }
    if (t == 0) {
        int bid = bi * 32 + bj;
        g_psum[bid] = rs[0]; g_pmin[bid] = rmn[0]; g_pmax[bid] = rmx[0];
    }
}

__global__ void k_dconsts() {
    __shared__ float rs[1024], rmn[1024], rmx[1024];
    int t = threadIdx.x;
    rs[t] = g_psum[t]; rmn[t] = g_pmin[t]; rmx[t] = g_pmax[t];
    __syncthreads();
    for (int o = 512; o; o >>= 1) {
        if (t < o) {
            rs[t] += rs[t + o];
            rmn[t] = fminf(rmn[t], rmn[t + o]);
            rmx[t] = fmaxf(rmx[t], rmx[t + o]);
        }
        __syncthreads();
    }
    if (t == 0) {
        float avg = rs[0] / ((float)N_ * (float)(N_ - 1));
        float mn = (rmn[0] < avg) ? 0.0f : rmn[0];
        float mx = rmx[0];
        if (mx == mn) mx = mn + 1.0f;
        g_dc[0] = avg; g_dc[1] = mn; g_dc[2] = 1.0f / (mx - mn);
    }
}

// D finalize: output pointer only 4B-aligned -> scalar stores
__global__ void k_dfinal(float* __restrict__ D) {
    float avg = g_dc[0], mn = g_dc[1], inv = g_dc[2];
    size_t base = ((size_t)blockIdx.x * 256 + threadIdx.x) * 4;
    float4 v = *(const float4*)(g_Draw + base);
    float vv[4] = { v.x, v.y, v.z, v.w };
#pragma unroll
    for (int j = 0; j < 4; j++) {
        size_t idx = base + j;
        int gi = (int)(idx >> 12);
        int gj = (int)(idx & 4095);
        float dt = (vv[j] < avg) ? 0.0f : vv[j];
        D[idx] = (gi == gj) ? 1.0f : (dt - mn) * inv;
    }
}

// ---------------- W split/transpose precompute ----------------
__global__ void k_wsplit(const float* __restrict__ Wp1, const float* __restrict__ Wq1,
                         const float* __restrict__ Wa,
                         const float* __restrict__ Wp2, const float* __restrict__ Wq2) {
    int idx = blockIdx.x * 256 + threadIdx.x;
    if (idx < 3 * 64 * 256) {
        int w = idx >> 14;
        int n = (idx >> 8) & 63;
        int k = idx & 255;
        const float* W = (w == 0) ? Wp1 : (w == 1) ? Wq1 : Wa;
        float x = W[k * 64 + n];
        __nv_bfloat16 h, l; bf16split(x, h, l);
        g_W1Th[idx] = h; g_W1Tl[idx] = l;
    }
    if (idx < 2 * 64 * 64) {
        int p = idx >> 12;
        int n = (idx >> 6) & 63;
        int k = idx & 63;
        const float* W = p ? Wq2 : Wp2;
        float x = W[k * 64 + n];
        __nv_bfloat16 h, l; bf16split(x, h, l);
        g_W2Th[idx] = h; g_W2Tl[idx] = l;
    }
}

// ---------------- GEMM1 (mma.sync bf16, manual frag loads — R8 proven) ----------------
#define G1_A_ELEM (128 * 72)
#define G1_B_ELEM (192 * 72)
#define G1_SMEM ((2 * G1_A_ELEM + 2 * G1_B_ELEM) * 2)

__global__ void __launch_bounds__(512)
k_gemm1_mma(const float* __restrict__ L, const float* __restrict__ Pw,
            const float* __restrict__ Nw, const int* __restrict__ C,
            const float* __restrict__ bp1, const float* __restrict__ bq1,
            const float* __restrict__ ba) {
    extern __shared__ __nv_bfloat16 sm1[];
    __nv_bfloat16* sAh = sm1;
    __nv_bfloat16* sAl = sAh + G1_A_ELEM;
    __nv_bfloat16* sBh = sAl + G1_A_ELEM;
    __nv_bfloat16* sBl = sBh + G1_B_ELEM;
    __shared__ float sMp[128], sMn[128], sBias[192];

    int t = threadIdx.x;
    int m0 = blockIdx.x * 128;
    int wid = t >> 5, lane = t & 31;
    int wr = wid >> 2, wc = wid & 3;        // 4x4 warps
    int g = lane >> 2, t4 = lane & 3;

    if (t < 128) {
        int m = m0 + t;
        int n = m / SEQ_, s = m - n * SEQ_;
        int st = C[2 * n], en = C[2 * n + 1];
        bool in = (s >= st && s <= en);
        sMp[t] = in ? Pw[n * SEQ_ + s] : 0.0f;
        sMn[t] = in ? 0.0f : Nw[n * SEQ_ + s];
    } else if (t < 320) {
        int c = t - 128;
        sBias[c] = (c < 64) ? bp1[c] : (c < 128) ? bq1[c - 64] : ba[c - 128];
    }

    float acc[2][6][4];
#pragma unroll
    for (int r = 0; r < 2; r++)
#pragma unroll
        for (int c = 0; c < 6; c++)
#pragma unroll
            for (int j = 0; j < 4; j++) acc[r][c][j] = 0.f;

    for (int kc = 0; kc < 4; kc++) {
        __syncthreads();
        for (int i = t; i < 2048; i += 512) {
            int r = i >> 4, k4 = (i & 15) * 4;
            float4 v = *(const float4*)(L + (size_t)(m0 + r) * 256 + kc * 64 + k4);
            float xs[4] = { v.x, v.y, v.z, v.w };
            __nv_bfloat16 h[4], l[4];
#pragma unroll
            for (int j = 0; j < 4; j++) bf16split(xs[j], h[j], l[j]);
            uint2 uh = { packbf2(h[0], h[1]), packbf2(h[2], h[3]) };
            uint2 ul = { packbf2(l[0], l[1]), packbf2(l[2], l[3]) };
            *(uint2*)(sAh + r * 72 + k4) = uh;
            *(uint2*)(sAl + r * 72 + k4) = ul;
        }
        for (int i = t; i < 1536; i += 512) {
            int n = i >> 3, k8 = (i & 7) * 8;
            size_t goff = (size_t)(n >> 6) * 16384 + (size_t)(n & 63) * 256 + kc * 64 + k8;
            *(uint4*)(sBh + n * 72 + k8) = *(const uint4*)(g_W1Th + goff);
            *(uint4*)(sBl + n * 72 + k8) = *(const uint4*)(g_W1Tl + goff);
        }
        __syncthreads();

#pragma unroll
        for (int pass = 0; pass < 3; pass++) {
            const __nv_bfloat16* A = (pass == 2) ? sAl : sAh;
            const __nv_bfloat16* B = (pass == 1) ? sBl : sBh;
#pragma unroll
            for (int ks = 0; ks < 4; ks++) {
                int k0 = ks * 16;
                uint32_t af[2][4];
#pragma unroll
                for (int rt = 0; rt < 2; rt++) {
                    int row = wr * 32 + rt * 16;
                    af[rt][0] = *(const uint32_t*)(A + (row + g) * 72 + k0 + 2 * t4);
                    af[rt][1] = *(const uint32_t*)(A + (row + g + 8) * 72 + k0 + 2 * t4);
                    af[rt][2] = *(const uint32_t*)(A + (row + g) * 72 + k0 + 2 * t4 + 8);
                    af[rt][3] = *(const uint32_t*)(A + (row + g + 8) * 72 + k0 + 2 * t4 + 8);
                }
#pragma unroll
                for (int ct = 0; ct < 6; ct++) {
                    int n = wc * 48 + ct * 8;
                    uint32_t b0 = *(const uint32_t*)(B + (n + g) * 72 + k0 + 2 * t4);
                    uint32_t b1 = *(const uint32_t*)(B + (n + g) * 72 + k0 + 2 * t4 + 8);
                    mma_bf16(acc[0][ct], af[0], b0, b1);
                    mma_bf16(acc[1][ct], af[1], b0, b1);
                }
            }
        }
    }

#pragma unroll
    for (int rt = 0; rt < 2; rt++) {
        int r0 = wr * 32 + rt * 16 + g;
        int r1 = r0 + 8;
        size_t m0r0 = (size_t)(m0 + r0);
        size_t m0r1 = (size_t)(m0 + r1);
        float mp0 = sMp[r0], mn0 = sMn[r0];
        float mp1 = sMp[r1], mn1 = sMn[r1];
#pragma unroll
        for (int ct = 0; ct < 6; ct++) {
            int nn = wc * 48 + ct * 8 + 2 * t4;
            float b0 = sBias[nn], b1 = sBias[nn + 1];
            if (nn < 128) {
                float s0 = (nn < 64) ? mp0 : mn0;
                float s1 = (nn < 64) ? mp1 : mn1;
                float h00 = fast_tanh(s0 * acc[rt][ct][0] + b0);
                float h01 = fast_tanh(s0 * acc[rt][ct][1] + b1);
                float h10 = fast_tanh(s1 * acc[rt][ct][2] + b0);
                float h11 = fast_tanh(s1 * acc[rt][ct][3] + b1);
                __nv_bfloat16 hh, hl, h2h, h2l;
                bf16split(h00, hh, hl); bf16split(h01, h2h, h2l);
                *(unsigned*)(&g_Hh[m0r0 * 128 + nn]) = packbf2(hh, h2h);
                *(unsigned*)(&g_Hl[m0r0 * 128 + nn]) = packbf2(hl, h2l);
                bf16split(h10, hh, hl); bf16split(h11, h2h, h2l);
                *(unsigned*)(&g_Hh[m0r1 * 128 + nn]) = packbf2(hh, h2h);
                *(unsigned*)(&g_Hl[m0r1 * 128 + nn]) = packbf2(hl, h2l);
            } else {
                int na = nn - 128;
                float s0 = mp0 + mn0, s1 = mp1 + mn1;
                float2 o0, o1;
                o0.x = fast_tanh(s0 * acc[rt][ct][0] + b0);
                o0.y = fast_tanh(s0 * acc[rt][ct][1] + b1);
                o1.x = fast_tanh(s1 * acc[rt][ct][2] + b0);
                o1.y = fast_tanh(s1 * acc[rt][ct][3] + b1);
                *(float2*)(g_TA + m0r0 * 64 + na) = o0;
                *(float2*)(g_TA + m0r1 * 64 + na) = o1;
            }
        }
    }
}

// ---------------- GEMM2 (mma.sync bf16, manual frag loads — R8 proven) ----------------
#define G2_H_ELEM (128 * 136)
#define G2_W_ELEM (2 * 64 * 72)
#define G2_SMEM ((2 * G2_H_ELEM + 2 * G2_W_ELEM) * 2)

__global__ void __launch_bounds__(512)
k_gemm2_mma(const float* __restrict__ bp2, const float* __restrict__ bq2) {
    extern __shared__ __nv_bfloat16 sm2[];
    __nv_bfloat16* sHh = sm2;
    __nv_bfloat16* sHl = sHh + G2_H_ELEM;
    __nv_bfloat16* sWh = sHl + G2_H_ELEM;
    __nv_bfloat16* sWl = sWh + G2_W_ELEM;
    __shared__ float sBias[128];

    int t = threadIdx.x;
    int m0 = blockIdx.x * 128;
    int wid = t >> 5, lane = t & 31;
    int wr = wid >> 2, wc = wid & 3;
    int g = lane >> 2, t4 = lane & 3;
    int region = wc >> 1;
    int kbase = region * 64;

    if (t < 128) sBias[t] = (t < 64) ? bp2[t] : bq2[t - 64];

    for (int i = t; i < 2048; i += 512) {
        int r = i >> 4, k8 = (i & 15) * 8;
        size_t goff = (size_t)(m0 + r) * 128 + k8;
        *(uint4*)(sHh + r * 136 + k8) = *(const uint4*)(g_Hh + goff);
        *(uint4*)(sHl + r * 136 + k8) = *(const uint4*)(g_Hl + goff);
    }
    for (int i = t; i < 1024; i += 512) {
        int rg = i >> 9, n = (i >> 3) & 63, k8 = (i & 7) * 8;
        size_t goff = (size_t)rg * 4096 + (size_t)n * 64 + k8;
        *(uint4*)(sWh + (rg * 64 + n) * 72 + k8) = *(const uint4*)(g_W2Th + goff);
        *(uint4*)(sWl + (rg * 64 + n) * 72 + k8) = *(const uint4*)(g_W2Tl + goff);
    }
    __syncthreads();

    float acc[2][4][4];
#pragma unroll
    for (int r = 0; r < 2; r++)
#pragma unroll
        for (int c = 0; c < 4; c++)
#pragma unroll
            for (int j = 0; j < 4; j++) acc[r][c][j] = 0.f;

#pragma unroll
    for (int pass = 0; pass < 3; pass++) {
        const __nv_bfloat16* A = (pass == 2) ? sHl : sHh;
        const __nv_bfloat16* B = (pass == 1) ? sWl : sWh;
#pragma unroll
        for (int ks = 0; ks < 4; ks++) {
            int k0 = kbase + ks * 16;
            uint32_t af[2][4];
#pragma unroll
            for (int rt = 0; rt < 2; rt++) {
                int row = wr * 32 + rt * 16;
                af[rt][0] = *(const uint32_t*)(A + (row + g) * 136 + k0 + 2 * t4);
                af[rt][1] = *(const uint32_t*)(A + (row + g + 8) * 136 + k0 + 2 * t4);
                af[rt][2] = *(const uint32_t*)(A + (row + g) * 136 + k0 + 2 * t4 + 8);
                af[rt][3] = *(const uint32_t*)(A + (row + g + 8) * 136 + k0 + 2 * t4 + 8);
            }
#pragma unroll
            for (int ct = 0; ct < 4; ct++) {
                int nl = (wc & 1) * 32 + ct * 8;
                int kk = ks * 16;
                const __nv_bfloat16* Bp = B + (region * 64 + nl + g) * 72 + kk + 2 * t4;
                uint32_t b0 = *(const uint32_t*)(Bp);
                uint32_t b1 = *(const uint32_t*)(Bp + 8);
                mma_bf16(acc[0][ct], af[0], b0, b1);
                mma_bf16(acc[1][ct], af[1], b0, b1);
            }
        }
    }

#pragma unroll
    for (int rt = 0; rt < 2; rt++) {
        int r0 = wr * 32 + rt * 16 + g;
        int r1 = r0 + 8;
        size_t m0r0 = (size_t)(m0 + r0);
        size_t m0r1 = (size_t)(m0 + r1);
#pragma unroll
        for (int ct = 0; ct < 4; ct++) {
            int nn = wc * 32 + ct * 8 + 2 * t4;
            float b0 = sBias[nn], b1 = sBias[nn + 1];
            float2 o0, o1;
            o0.x = fast_tanh(acc[rt][ct][0] + b0);
            o0.y = fast_tanh(acc[rt][ct][1] + b1);
            o1.x = fast_tanh(acc[rt][ct][2] + b0);
            o1.y = fast_tanh(acc[rt][ct][3] + b1);
            *(float2*)(g_T2 + m0r0 * 128 + nn) = o0;
            *(float2*)(g_T2 + m0r1 * 128 + nn) = o1;
        }
    }
}

// ---------------- R1: final_feature mean ----------------
__global__ void k_r1(float* __restrict__ out_ff) {
    int n = blockIdx.x, t = threadIdx.x;   // 64 threads
    float s = 0.f;
#pragma unroll 8
    for (int q = 0; q < SEQ_; q++) s += g_TA[((size_t)n * SEQ_ + q) * 64 + t];
    out_ff[n * 64 + t] = s * (1.0f / (float)SEQ_);
}

// ---------------- R2: pos/neg vec means + sq-norms + bf16 split ----------------
__global__ void k_r2() {
    __shared__ float ws[4];
    int n = blockIdx.x, t = threadIdx.x;   // 128 threads
    float s = 0.f;
#pragma unroll 8
    for (int q = 0; q < SEQ_; q++) s += g_T2[((size_t)n * SEQ_ + q) * 128 + t];
    float v = s * (1.0f / (float)SEQ_);
    __nv_bfloat16 h, l; bf16split(v, h, l);
    if (t < 64) {
        g_posvec[n * 64 + t] = v;
        g_pvh[n * 64 + t] = h; g_pvl[n * 64 + t] = l;
    } else {
        g_negvec[n * 64 + (t - 64)] = v;
        g_nvh[n * 64 + (t - 64)] = h; g_nvl[n * 64 + (t - 64)] = l;
    }
    float sq = v * v;
#pragma unroll
    for (int o = 16; o; o >>= 1) sq += __shfl_xor_sync(0xffffffffu, sq, o);
    if ((t & 31) == 0) ws[t >> 5] = sq;
    __syncthreads();
    if (t == 0) {
        g_psn[n] = ws[0] + ws[1];
        g_nsn[n] = ws[2] + ws[3];
    }
}

// ---------------- K8: similarity sums (tensor-core, MANUAL frag loads) ----------------
// 256 thr = 8 warps (4 M x 2 N), warp tile 32x64, K=64, 3 split passes, 2 targets.
#define SIM_STR 72
#define SIM_TILE (128 * SIM_STR)
#define SIMTC_SMEM (6 * SIM_TILE * 2)   // 110592 bytes
__global__ void __launch_bounds__(256)
k_sims_tc() {
    extern __shared__ __nv_bfloat16 ssm[];
    __nv_bfloat16* pIh = ssm;
    __nv_bfloat16* pIl = pIh + SIM_TILE;
    __nv_bfloat16* pJh = pIl + SIM_TILE;
    __nv_bfloat16* pJl = pJh + SIM_TILE;
    __nv_bfloat16* nJh = pJl + SIM_TILE;
    __nv_bfloat16* nJl = nJh + SIM_TILE;
    __shared__ float snI[128], snP[128], snN[128];
    __shared__ float rp[256], rn[256];

    int bi = blockIdx.y, bj = blockIdx.x, t = threadIdx.x;
    int wid = t >> 5, lane = t & 31;
    int wr = wid >> 1, wc = wid & 1;
    int g = lane >> 2, t4 = lane & 3;

    for (int i = t; i < 1024; i += 256) {   // 128 rows x 8 uint4
        int r = i >> 3, q = (i & 7) * 8;
        *(uint4*)(pIh + r * SIM_STR + q) = *(const uint4*)(g_pvh + (bi * 128 + r) * 64 + q);
        *(uint4*)(pIl + r * SIM_STR + q) = *(const uint4*)(g_pvl + (bi * 128 + r) * 64 + q);
        *(uint4*)(pJh + r * SIM_STR + q) = *(const uint4*)(g_pvh + (bj * 128 + r) * 64 + q);
        *(uint4*)(pJl + r * SIM_STR + q) = *(const uint4*)(g_pvl + (bj * 128 + r) * 64 + q);
        *(uint4*)(nJh + r * SIM_STR + q) = *(const uint4*)(g_nvh + (bj * 128 + r) * 64 + q);
        *(uint4*)(nJl + r * SIM_STR + q) = *(const uint4*)(g_nvl + (bj * 128 + r) * 64 + q);
    }
    if (t < 128) { snI[t] = g_psn[bi * 128 + t]; snN[t] = g_nsn[bj * 128 + t]; }
    else snP[t - 128] = g_psn[bj * 128 + (t - 128)];
    __syncthreads();

    float lp = 0.f, ln = 0.f;
#pragma unroll
    for (int targ = 0; targ < 2; targ++) {
        const __nv_bfloat16* Bh = targ ? nJh : pJh;
        const __nv_bfloat16* Bl = targ ? nJl : pJl;
        float acc[2][8][4];
#pragma unroll
        for (int r = 0; r < 2; r++)
#pragma unroll
            for (int c = 0; c < 8; c++)
#pragma unroll
                for (int j = 0; j < 4; j++) acc[r][c][j] = 0.f;

#pragma unroll
        for (int pass = 0; pass < 3; pass++) {
            const __nv_bfloat16* A = (pass == 2) ? pIl : pIh;
            const __nv_bfloat16* B = (pass == 1) ? Bl : Bh;
#pragma unroll
            for (int ks = 0; ks < 4; ks++) {
                int k0 = ks * 16;
                uint32_t af[2][4];
#pragma unroll
                for (int rt = 0; rt < 2; rt++) {
                    int row = wr * 32 + rt * 16;
                    af[rt][0] = *(const uint32_t*)(A + (row + g) * SIM_STR + k0 + 2 * t4);
                    af[rt][1] = *(const uint32_t*)(A + (row + g + 8) * SIM_STR + k0 + 2 * t4);
                    af[rt][2] = *(const uint32_t*)(A + (row + g) * SIM_STR + k0 + 2 * t4 + 8);
                    af[rt][3] = *(const uint32_t*)(A + (row + g + 8) * SIM_STR + k0 + 2 * t4 + 8);
                }
#pragma unroll
                for (int ct = 0; ct < 8; ct++) {
                    int n = wc * 64 + ct * 8;
                    uint32_t b0 = *(const uint32_t*)(B + (n + g) * SIM_STR + k0 + 2 * t4);
                    uint32_t b1 = *(const uint32_t*)(B + (n + g) * SIM_STR + k0 + 2 * t4 + 8);
                    mma_bf16(acc[0][ct], af[0], b0, b1);
                    mma_bf16(acc[1][ct], af[1], b0, b1);
                }
            }
        }

        const float* snX = targ ? snN : snP;
        float tot = 0.f;
#pragma unroll
        for (int rt = 0; rt < 2; rt++) {
#pragma unroll
            for (int ct = 0; ct < 8; ct++) {
                int rl = wr * 32 + rt * 16 + g;
                int cl = wc * 64 + ct * 8 + 2 * t4;
                float nI0 = snI[rl], nI1 = snI[rl + 8];
                float c0 = snX[cl], c1 = snX[cl + 1];
                float sqv[4] = { nI0 + c0 - 2.f * acc[rt][ct][0],
                                 nI0 + c1 - 2.f * acc[rt][ct][1],
                                 nI1 + c0 - 2.f * acc[rt][ct][2],
                                 nI1 + c1 - 2.f * acc[rt][ct][3] };
#pragma unroll
                for (int j = 0; j < 4; j++) {
                    float sq = fmaxf(sqv[j], 0.0f);
                    float d = (sq > 0.0f) ? sqrtf(sq) : 0.0f;
                    tot += __expf(-d);
                }
            }
        }
        if (targ == 0) lp = tot; else ln = tot;
    }
    rp[t] = lp; rn[t] = ln;
    __syncthreads();
    for (int o = 128; o; o >>= 1) {
        if (t < o) { rp[t] += rp[t + o]; rn[t] += rn[t + o]; }
        __syncthreads();
    }
    if (t == 0) {
        int bid = bi * 32 + bj;
        g_sp[bid] = rp[0]; g_sn[bid] = rn[0];
    }
}

__global__ void k_loss(float* __restrict__ out_loss) {
    __shared__ float rp[1024], rn[1024];
    int t = threadIdx.x;
    rp[t] = g_sp[t]; rn[t] = g_sn[t];
    __syncthreads();
    for (int o = 512; o; o >>= 1) {
        if (t < o) { rp[t] += rp[t + o]; rn[t] += rn[t + o]; }
        __syncthreads();
    }
    if (t == 0) out_loss[0] = -logf(rp[0] / rn[0]);
}

// ---------------- launch ----------------
extern "C" void kernel_launch(void* const* d_in, const int* in_sizes, int n_in,
                              void* d_out, int out_size) {
    const float* A     = (const float*)d_in[0];
    const int*   C     = (const int*)d_in[1];
    const float* L     = (const float*)d_in[2];
    const float* W1    = (const float*)d_in[3];
    const float* b1    = (const float*)d_in[4];
    const float* gam   = (const float*)d_in[5];
    const float* bet   = (const float*)d_in[6];
    const float* sig   = (const float*)d_in[7];
    const float* Pw    = (const float*)d_in[8];
    const float* Nw    = (const float*)d_in[9];
    const float* Wp1   = (const float*)d_in[10];
    const float* bp1   = (const float*)d_in[11];
    const float* Wp2   = (const float*)d_in[12];
    const float* bp2   = (const float*)d_in[13];
    const float* Wq1   = (const float*)d_in[14];
    const float* bq1   = (const float*)d_in[15];
    const float* Wq2   = (const float*)d_in[16];
    const float* bq2   = (const float*)d_in[17];
    const float* Wa    = (const float*)d_in[18];
    const float* ba    = (const float*)d_in[19];

    float* out = (float*)d_out;
    float* out_ff   = out;                    // [4096*64]
    float* out_loss = out + N_ * RED_;        // [1]
    float* out_D    = out + N_ * RED_ + 1;    // [4096*4096], only 4B-aligned!

    cudaFuncSetAttribute(k_gemm1_mma, cudaFuncAttributeMaxDynamicSharedMemorySize, G1_SMEM);
    cudaFuncSetAttribute(k_gemm2_mma, cudaFuncAttributeMaxDynamicSharedMemorySize, G2_SMEM);
    cudaFuncSetAttribute(k_sims_tc, cudaFuncAttributeMaxDynamicSharedMemorySize, SIMTC_SMEM);

    k_wsplit<<<192, 256>>>(Wp1, Wq1, Wa, Wp2, Wq2);
    k_gather_h<<<N_, 128>>>(A, C, W1, b1);
    k_bnstats<<<1, 1024>>>();
    k_emb<<<512, 256>>>(gam, bet);
    k_dstats<<<dim3(32, 32), 256>>>(sig);
    k_dconsts<<<1, 1024>>>();
    k_dfinal<<<(N_ * (N_ / 4)) / 256, 256>>>(out_D);
    k_gemm1_mma<<<M1_ / 128, 512, G1_SMEM>>>(L, Pw, Nw, C, bp1, bq1, ba);
    k_gemm2_mma<<<M1_ / 128, 512, G2_SMEM>>>(bp2, bq2);
    k_r1<<<N_, 64>>>(out_ff);
    k_r2<<<N_, 128>>>();
    k_sims_tc<<<dim3(32, 32), 256, SIMTC_SMEM>>>();
    k_loss<<<1, 1024>>>(out_loss);
}

// round 15
// speedup vs baseline: 1.6288x; 1.0910x over previous
#include <cuda_runtime.h>
#include <cuda_bf16.h>
#include <math.h>
#include <stdint.h>

#define N_   4096
#define SEQ_ 41
#define VEC_ 15
#define T_   8
#define EMB_ 32
#define LDIM_ 256
#define RED_ 64
#define M1_  (N_ * SEQ_)   // 167936 rows = 1312 tiles of 128

// ---------------- scratch (device globals; no allocation) ----------------
__device__ float g_h[N_ * EMB_];
__device__ float g_emb[N_ * EMB_];
__device__ float g_sqn[N_];
__device__ float g_mu[EMB_];
__device__ float g_rstd[EMB_];
__device__ float g_psum[1024];
__device__ float g_pmin[1024];
__device__ float g_pmax[1024];
__device__ float g_dc[3];
__device__ float g_posvec[N_ * RED_];
__device__ float g_negvec[N_ * RED_];
__device__ float g_psn[N_];
__device__ float g_nsn[N_];
__device__ float g_TA[(size_t)M1_ * 64];
__device__ float g_T2[(size_t)M1_ * 128];
__device__ float g_Draw[(size_t)N_ * N_];
__device__ float g_sp[1024];
__device__ float g_sn[1024];
// bf16-split intermediates
__device__ __nv_bfloat16 g_Hh[(size_t)M1_ * 128];
__device__ __nv_bfloat16 g_Hl[(size_t)M1_ * 128];
__device__ __nv_bfloat16 g_W1Th[3 * 64 * 256];
__device__ __nv_bfloat16 g_W1Tl[3 * 64 * 256];
__device__ __nv_bfloat16 g_W2Th[2 * 64 * 64];
__device__ __nv_bfloat16 g_W2Tl[2 * 64 * 64];
__device__ __nv_bfloat16 g_pvh[N_ * 64], g_pvl[N_ * 64];
__device__ __nv_bfloat16 g_nvh[N_ * 64], g_nvl[N_ * 64];

__device__ __forceinline__ float fast_tanh(float x) {
    float e = __expf(2.0f * x);
    return 1.0f - 2.0f / (e + 1.0f);
}
__device__ __forceinline__ void bf16split(float x, __nv_bfloat16& h, __nv_bfloat16& l) {
    h = __float2bfloat16(x);
    l = __float2bfloat16(x - __bfloat162float(h));
}
__device__ __forceinline__ unsigned packbf2(__nv_bfloat16 a, __nv_bfloat16 b) {
    __nv_bfloat162 t = __nv_bfloat162(a, b);
    return *reinterpret_cast<unsigned*>(&t);
}
__device__ __forceinline__ float tf32_round(float x) {
    float r;
    asm("cvt.rna.tf32.f32 %0, %1;" : "=f"(r) : "f"(x));
    return r;
}

// bf16 warp MMA: D(16x8,f32) += A(16x16,row) * B(16x8,col)
__device__ __forceinline__ void mma_bf16(float c[4], const uint32_t a[4],
                                         uint32_t b0, uint32_t b1) {
    asm volatile(
        "mma.sync.aligned.m16n8k16.row.col.f32.bf16.bf16.f32 "
        "{%0,%1,%2,%3}, {%4,%5,%6,%7}, {%8,%9}, {%0,%1,%2,%3};"
        : "+f"(c[0]), "+f"(c[1]), "+f"(c[2]), "+f"(c[3])
        : "r"(a[0]), "r"(a[1]), "r"(a[2]), "r"(a[3]), "r"(b0), "r"(b1));
}
// tf32 warp MMA: D(16x8,f32) += A(16x8,row) * B(8x8,col)
__device__ __forceinline__ void mma_tf32(float c[4], const uint32_t a[4],
                                         uint32_t b0, uint32_t b1) {
    asm volatile(
        "mma.sync.aligned.m16n8k8.row.col.f32.tf32.tf32.f32 "
        "{%0,%1,%2,%3}, {%4,%5,%6,%7}, {%8,%9}, {%0,%1,%2,%3};"
        : "+f"(c[0]), "+f"(c[1]), "+f"(c[2]), "+f"(c[3])
        : "r"(a[0]), "r"(a[1]), "r"(a[2]), "r"(a[3]), "r"(b0), "r"(b1));
}

// ---------------- K1: gather + interp + h = tanh(flat@W1 + b1) ----------------
__global__ void k_gather_h(const float* __restrict__ A, const int* __restrict__ C,
                           const float* __restrict__ W1, const float* __restrict__ b1) {
    __shared__ float flat[120];
    int n = blockIdx.x;
    int t = threadIdx.x;
    int start = C[2 * n], end = C[2 * n + 1];
    int len = end - start + 1;
    if (t < 120) {
        int j = t / VEC_, v = t % VEC_;
        float scale = (float)len / (float)T_;
        float src = fmaxf(scale * ((float)j + 0.5f) - 0.5f, 0.0f);
        int i0 = min((int)floorf(src), len - 1);
        int i1 = min(i0 + 1, len - 1);
        float w = src - (float)i0;
        const float* Ar = A + (size_t)n * SEQ_ * VEC_;
        float g0 = Ar[(start + i0) * VEC_ + v];
        float g1 = Ar[(start + i1) * VEC_ + v];
        flat[t] = (1.0f - w) * g0 + w * g1;
    }
    __syncthreads();
    if (t < 32) {
        float acc = b1[t];
#pragma unroll
        for (int k = 0; k < 120; k++) acc += flat[k] * W1[k * 32 + t];
        g_h[n * 32 + t] = tanhf(acc);
    }
}

// ---------------- K2: batchnorm stats ----------------
__global__ void k_bnstats() {
    __shared__ float ssum[32][33];
    __shared__ float ssq[32][33];
    int c = threadIdx.x & 31, g = threadIdx.x >> 5;
    float s = 0.f, q = 0.f;
    for (int n = g; n < N_; n += 32) {
        float v = g_h[n * 32 + c];
        s += v; q += v * v;
    }
    ssum[g][c] = s; ssq[g][c] = q;
    __syncthreads();
    if (threadIdx.x < 32) {
        float S = 0.f, Q = 0.f;
        for (int gg = 0; gg < 32; gg++) { S += ssum[gg][threadIdx.x]; Q += ssq[gg][threadIdx.x]; }
        float mu = S / (float)N_;
        float var = Q / (float)N_ - mu * mu;
        g_mu[threadIdx.x] = mu;
        g_rstd[threadIdx.x] = rsqrtf(var + 1e-5f);
    }
}

// ---------------- K3: emb + row sq-norms ----------------
__global__ void k_emb(const float* __restrict__ gamma, const float* __restrict__ beta) {
    int idx = blockIdx.x * 256 + threadIdx.x;
    int c = idx & 31;
    float e = gamma[c] * (g_h[idx] - g_mu[c]) * g_rstd[c] + beta[c];
    g_emb[idx] = e;
    float sq = e * e;
#pragma unroll
    for (int o = 16; o; o >>= 1) sq += __shfl_xor_sync(0xffffffffu, sq, o);
    if (c == 0) g_sqn[idx >> 5] = sq;
}

// ---------------- K4: D stats (tf32 3-pass split tensor-core GEMM) ----------------
// 128x128 tile, 256 thr = 8 warps (4M x 2N), warp tile 32x64, K=32 (4 x k8).
// stride 36 floats -> frag-load bank = 4g+t4+const = lane -> conflict-free.
#define DT_STR 36
#define DT_SMEM (4 * 128 * DT_STR * 4)   // 73728 bytes
__global__ void __launch_bounds__(256)
k_dstats_tf32(const float* __restrict__ sigma_p) {
    extern __shared__ float dsf[];
    float* sIh = dsf;
    float* sIl = sIh + 128 * DT_STR;
    float* sJh = sIl + 128 * DT_STR;
    float* sJl = sJh + 128 * DT_STR;
    __shared__ float snI[128], snJ[128];
    __shared__ float rs[256], rmn[256], rmx[256];

    int bi = blockIdx.y, bj = blockIdx.x, t = threadIdx.x;
    int wid = t >> 5, lane = t & 31;
    int wr = wid >> 1, wc = wid & 1;
    int g = lane >> 2, t4 = lane & 3;

    for (int i = t; i < 128 * 32; i += 256) {
        int r = i >> 5, k = i & 31;
        float eI = g_emb[(bi * 128 + r) * 32 + k];
        float eJ = g_emb[(bj * 128 + r) * 32 + k];
        float hI = tf32_round(eI), hJ = tf32_round(eJ);
        sIh[r * DT_STR + k] = hI; sIl[r * DT_STR + k] = tf32_round(eI - hI);
        sJh[r * DT_STR + k] = hJ; sJl[r * DT_STR + k] = tf32_round(eJ - hJ);
    }
    if (t < 128) snI[t] = g_sqn[bi * 128 + t];
    else snJ[t - 128] = g_sqn[bj * 128 + (t - 128)];
    __syncthreads();

    float acc[2][8][4];
#pragma unroll
    for (int r = 0; r < 2; r++)
#pragma unroll
        for (int c = 0; c < 8; c++)
#pragma unroll
            for (int j = 0; j < 4; j++) acc[r][c][j] = 0.f;

#pragma unroll
    for (int pass = 0; pass < 3; pass++) {
        const float* A = (pass == 2) ? sIl : sIh;
        const float* B = (pass == 1) ? sJl : sJh;
#pragma unroll
        for (int ks = 0; ks < 4; ks++) {
            int k0 = ks * 8;
            uint32_t af[2][4];
#pragma unroll
            for (int rt = 0; rt < 2; rt++) {
                int row = wr * 32 + rt * 16;
                af[rt][0] = __float_as_uint(A[(row + g) * DT_STR + k0 + t4]);
                af[rt][1] = __float_as_uint(A[(row + g + 8) * DT_STR + k0 + t4]);
                af[rt][2] = __float_as_uint(A[(row + g) * DT_STR + k0 + t4 + 4]);
                af[rt][3] = __float_as_uint(A[(row + g + 8) * DT_STR + k0 + t4 + 4]);
            }
#pragma unroll
            for (int ct = 0; ct < 8; ct++) {
                int n = wc * 64 + ct * 8;
                uint32_t b0 = __float_as_uint(B[(n + g) * DT_STR + k0 + t4]);
                uint32_t b1 = __float_as_uint(B[(n + g) * DT_STR + k0 + t4 + 4]);
                mma_tf32(acc[0][ct], af[0], b0, b1);
                mma_tf32(acc[1][ct], af[1], b0, b1);
            }
        }
    }

    float inv2s;
    { float sg = sigma_p[0]; inv2s = 0.5f / (sg * sg); }
    float lsum = 0.f, lmin = 3.4e38f, lmax = -3.4e38f;
#pragma unroll
    for (int rt = 0; rt < 2; rt++) {
#pragma unroll
        for (int ct = 0; ct < 8; ct++) {
            int rl0 = wr * 32 + rt * 16 + g;
            int cl = wc * 64 + ct * 8 + 2 * t4;
            int gi0 = bi * 128 + rl0, gi1 = gi0 + 8;
            int gj0 = bj * 128 + cl, gj1 = gj0 + 1;
            float nI0 = snI[rl0], nI1 = snI[rl0 + 8];
            float nJ0 = snJ[cl], nJ1 = snJ[cl + 1];
            float v[4];
            float sqv[4] = { nI0 + nJ0 - 2.f * acc[rt][ct][0],
                             nI0 + nJ1 - 2.f * acc[rt][ct][1],
                             nI1 + nJ0 - 2.f * acc[rt][ct][2],
                             nI1 + nJ1 - 2.f * acc[rt][ct][3] };
#pragma unroll
            for (int j = 0; j < 4; j++) {
                float sq = fmaxf(sqv[j], 0.0f);
                float d = (sq > 0.0f) ? sqrtf(sq) : 0.0f;
                v[j] = __expf(-d * inv2s);
            }
            *(float2*)(g_Draw + (size_t)gi0 * N_ + gj0) = make_float2(v[0], v[1]);
            *(float2*)(g_Draw + (size_t)gi1 * N_ + gj0) = make_float2(v[2], v[3]);
            int gis[4] = { gi0, gi0, gi1, gi1 };
            int gjs[4] = { gj0, gj1, gj0, gj1 };
#pragma unroll
            for (int j = 0; j < 4; j++) {
                if (gis[j] != gjs[j]) {
                    lsum += v[j];
                    lmin = fminf(lmin, v[j]);
                    lmax = fmaxf(lmax, v[j]);
                }
            }
        }
    }
    rs[t] = lsum; rmn[t] = lmin; rmx[t] = lmax;
    __syncthreads();
    for (int o = 128; o; o >>= 1) {
        if (t < o) {
            rs[t] += rs[t + o];
            rmn[t] = fminf(rmn[t], rmn[t + o]);
            rmx[t] = fmaxf(rmx[t], rmx[t + o]);
        }
        __syncthreads();
    }
    if (t == 0) {
        int bid = bi * 32 + bj;
        g_psum[bid] = rs[0]; g_pmin[bid] = rmn[0]; g_pmax[bid] = rmx[0];
    }
}

__global__ void k_dconsts() {
    __shared__ float rs[1024], rmn[1024], rmx[1024];
    int t = threadIdx.x;
    rs[t] = g_psum[t]; rmn[t] = g_pmin[t]; rmx[t] = g_pmax[t];
    __syncthreads();
    for (int o = 512; o; o >>= 1) {
        if (t < o) {
            rs[t] += rs[t + o];
            rmn[t] = fminf(rmn[t], rmn[t + o]);
            rmx[t] = fmaxf(rmx[t], rmx[t + o]);
        }
        __syncthreads();
    }
    if (t == 0) {
        float avg = rs[0] / ((float)N_ * (float)(N_ - 1));
        float mn = (rmn[0] < avg) ? 0.0f : rmn[0];
        float mx = rmx[0];
        if (mx == mn) mx = mn + 1.0f;
        g_dc[0] = avg; g_dc[1] = mn; g_dc[2] = 1.0f / (mx - mn);
    }
}

// D finalize: output pointer only 4B-aligned -> scalar stores
__global__ void k_dfinal(float* __restrict__ D) {
    float avg = g_dc[0], mn = g_dc[1], inv = g_dc[2];
    size_t base = ((size_t)blockIdx.x * 256 + threadIdx.x) * 4;
    float4 v = *(const float4*)(g_Draw + base);
    float vv[4] = { v.x, v.y, v.z, v.w };
#pragma unroll
    for (int j = 0; j < 4; j++) {
        size_t idx = base + j;
        int gi = (int)(idx >> 12);
        int gj = (int)(idx & 4095);
        float dt = (vv[j] < avg) ? 0.0f : vv[j];
        D[idx] = (gi == gj) ? 1.0f : (dt - mn) * inv;
    }
}

// ---------------- W split/transpose precompute ----------------
__global__ void k_wsplit(const float* __restrict__ Wp1, const float* __restrict__ Wq1,
                         const float* __restrict__ Wa,
                         const float* __restrict__ Wp2, const float* __restrict__ Wq2) {
    int idx = blockIdx.x * 256 + threadIdx.x;
    if (idx < 3 * 64 * 256) {
        int w = idx >> 14;
        int n = (idx >> 8) & 63;
        int k = idx & 255;
        const float* W = (w == 0) ? Wp1 : (w == 1) ? Wq1 : Wa;
        float x = W[k * 64 + n];
        __nv_bfloat16 h, l; bf16split(x, h, l);
        g_W1Th[idx] = h; g_W1Tl[idx] = l;
    }
    if (idx < 2 * 64 * 64) {
        int p = idx >> 12;
        int n = (idx >> 6) & 63;
        int k = idx & 63;
        const float* W = p ? Wq2 : Wp2;
        float x = W[k * 64 + n];
        __nv_bfloat16 h, l; bf16split(x, h, l);
        g_W2Th[idx] = h; g_W2Tl[idx] = l;
    }
}

// ---------------- GEMM1 (mma.sync bf16, manual frag loads + A-prefetch) ----------------
#define G1_A_ELEM (128 * 72)
#define G1_B_ELEM (192 * 72)
#define G1_SMEM ((2 * G1_A_ELEM + 2 * G1_B_ELEM) * 2)

__global__ void __launch_bounds__(512)
k_gemm1_mma(const float* __restrict__ L, const float* __restrict__ Pw,
            const float* __restrict__ Nw, const int* __restrict__ C,
            const float* __restrict__ bp1, const float* __restrict__ bq1,
            const float* __restrict__ ba) {
    extern __shared__ __nv_bfloat16 sm1[];
    __nv_bfloat16* sAh = sm1;
    __nv_bfloat16* sAl = sAh + G1_A_ELEM;
    __nv_bfloat16* sBh = sAl + G1_A_ELEM;
    __nv_bfloat16* sBl = sBh + G1_B_ELEM;
    __shared__ float sMp[128], sMn[128], sBias[192];

    int t = threadIdx.x;
    int m0 = blockIdx.x * 128;
    int wid = t >> 5, lane = t & 31;
    int wr = wid >> 2, wc = wid & 3;        // 4x4 warps
    int g = lane >> 2, t4 = lane & 3;

    if (t < 128) {
        int m = m0 + t;
        int n = m / SEQ_, s = m - n * SEQ_;
        int st = C[2 * n], en = C[2 * n + 1];
        bool in = (s >= st && s <= en);
        sMp[t] = in ? Pw[n * SEQ_ + s] : 0.0f;
        sMn[t] = in ? 0.0f : Nw[n * SEQ_ + s];
    } else if (t < 320) {
        int c = t - 128;
        sBias[c] = (c < 64) ? bp1[c] : (c < 128) ? bq1[c - 64] : ba[c - 128];
    }

    float acc[2][6][4];
#pragma unroll
    for (int r = 0; r < 2; r++)
#pragma unroll
        for (int c = 0; c < 6; c++)
#pragma unroll
            for (int j = 0; j < 4; j++) acc[r][c][j] = 0.f;

    // A-chunk prefetch registers (chunk 0)
    int pr_r = t >> 4, pr_k4 = (t & 15) * 4;   // each thread owns rows pr_r + i*32
    float4 pre[4];
#pragma unroll
    for (int i = 0; i < 4; i++) {
        int r = pr_r + i * 32;
        pre[i] = *(const float4*)(L + (size_t)(m0 + r) * 256 + pr_k4);
    }

    for (int kc = 0; kc < 4; kc++) {
        __syncthreads();
        // store prefetched A chunk (split fp32 -> hi/lo bf16)
#pragma unroll
        for (int i = 0; i < 4; i++) {
            int r = pr_r + i * 32;
            float xs[4] = { pre[i].x, pre[i].y, pre[i].z, pre[i].w };
            __nv_bfloat16 h[4], l[4];
#pragma unroll
            for (int j = 0; j < 4; j++) bf16split(xs[j], h[j], l[j]);
            uint2 uh = { packbf2(h[0], h[1]), packbf2(h[2], h[3]) };
            uint2 ul = { packbf2(l[0], l[1]), packbf2(l[2], l[3]) };
            *(uint2*)(sAh + r * 72 + pr_k4) = uh;
            *(uint2*)(sAl + r * 72 + pr_k4) = ul;
        }
        // B stage (L2-hot weights)
        for (int i = t; i < 1536; i += 512) {
            int n = i >> 3, k8 = (i & 7) * 8;
            size_t goff = (size_t)(n >> 6) * 16384 + (size_t)(n & 63) * 256 + kc * 64 + k8;
            *(uint4*)(sBh + n * 72 + k8) = *(const uint4*)(g_W1Th + goff);
            *(uint4*)(sBl + n * 72 + k8) = *(const uint4*)(g_W1Tl + goff);
        }
        __syncthreads();
        // prefetch next A chunk — retires under the MMA section below
        if (kc < 3) {
#pragma unroll
            for (int i = 0; i < 4; i++) {
                int r = pr_r + i * 32;
                pre[i] = *(const float4*)(L + (size_t)(m0 + r) * 256 + (kc + 1) * 64 + pr_k4);
            }
        }

#pragma unroll
        for (int pass = 0; pass < 3; pass++) {
            const __nv_bfloat16* A = (pass == 2) ? sAl : sAh;
            const __nv_bfloat16* B = (pass == 1) ? sBl : sBh;
#pragma unroll
            for (int ks = 0; ks < 4; ks++) {
                int k0 = ks * 16;
                uint32_t af[2][4];
#pragma unroll
                for (int rt = 0; rt < 2; rt++) {
                    int row = wr * 32 + rt * 16;
                    af[rt][0] = *(const uint32_t*)(A + (row + g) * 72 + k0 + 2 * t4);
                    af[rt][1] = *(const uint32_t*)(A + (row + g + 8) * 72 + k0 + 2 * t4);
                    af[rt][2] = *(const uint32_t*)(A + (row + g) * 72 + k0 + 2 * t4 + 8);
                    af[rt][3] = *(const uint32_t*)(A + (row + g + 8) * 72 + k0 + 2 * t4 + 8);
                }
#pragma unroll
                for (int ct = 0; ct < 6; ct++) {
                    int n = wc * 48 + ct * 8;
                    uint32_t b0 = *(const uint32_t*)(B + (n + g) * 72 + k0 + 2 * t4);
                    uint32_t b1 = *(const uint32_t*)(B + (n + g) * 72 + k0 + 2 * t4 + 8);
                    mma_bf16(acc[0][ct], af[0], b0, b1);
                    mma_bf16(acc[1][ct], af[1], b0, b1);
                }
            }
        }
    }

#pragma unroll
    for (int rt = 0; rt < 2; rt++) {
        int r0 = wr * 32 + rt * 16 + g;
        int r1 = r0 + 8;
        size_t m0r0 = (size_t)(m0 + r0);
        size_t m0r1 = (size_t)(m0 + r1);
        float mp0 = sMp[r0], mn0 = sMn[r0];
        float mp1 = sMp[r1], mn1 = sMn[r1];
#pragma unroll
        for (int ct = 0; ct < 6; ct++) {
            int nn = wc * 48 + ct * 8 + 2 * t4;
            float b0 = sBias[nn], b1 = sBias[nn + 1];
            if (nn < 128) {
                float s0 = (nn < 64) ? mp0 : mn0;
                float s1 = (nn < 64) ? mp1 : mn1;
                float h00 = fast_tanh(s0 * acc[rt][ct][0] + b0);
                float h01 = fast_tanh(s0 * acc[rt][ct][1] + b1);
                float h10 = fast_tanh(s1 * acc[rt][ct][2] + b0);
                float h11 = fast_tanh(s1 * acc[rt][ct][3] + b1);
                __nv_bfloat16 hh, hl, h2h, h2l;
                bf16split(h00, hh, hl); bf16split(h01, h2h, h2l);
                *(unsigned*)(&g_Hh[m0r0 * 128 + nn]) = packbf2(hh, h2h);
                *(unsigned*)(&g_Hl[m0r0 * 128 + nn]) = packbf2(hl, h2l);
                bf16split(h10, hh, hl); bf16split(h11, h2h, h2l);
                *(unsigned*)(&g_Hh[m0r1 * 128 + nn]) = packbf2(hh, h2h);
                *(unsigned*)(&g_Hl[m0r1 * 128 + nn]) = packbf2(hl, h2l);
            } else {
                int na = nn - 128;
                float s0 = mp0 + mn0, s1 = mp1 + mn1;
                float2 o0, o1;
                o0.x = fast_tanh(s0 * acc[rt][ct][0] + b0);
                o0.y = fast_tanh(s0 * acc[rt][ct][1] + b1);
                o1.x = fast_tanh(s1 * acc[rt][ct][2] + b0);
                o1.y = fast_tanh(s1 * acc[rt][ct][3] + b1);
                *(float2*)(g_TA + m0r0 * 64 + na) = o0;
                *(float2*)(g_TA + m0r1 * 64 + na) = o1;
            }
        }
    }
}

// ---------------- GEMM2 (mma.sync bf16, manual frag loads — R8 proven) ----------------
#define G2_H_ELEM (128 * 136)
#define G2_W_ELEM (2 * 64 * 72)
#define G2_SMEM ((2 * G2_H_ELEM + 2 * G2_W_ELEM) * 2)

__global__ void __launch_bounds__(512)
k_gemm2_mma(const float* __restrict__ bp2, const float* __restrict__ bq2) {
    extern __shared__ __nv_bfloat16 sm2[];
    __nv_bfloat16* sHh = sm2;
    __nv_bfloat16* sHl = sHh + G2_H_ELEM;
    __nv_bfloat16* sWh = sHl + G2_H_ELEM;
    __nv_bfloat16* sWl = sWh + G2_W_ELEM;
    __shared__ float sBias[128];

    int t = threadIdx.x;
    int m0 = blockIdx.x * 128;
    int wid = t >> 5, lane = t & 31;
    int wr = wid >> 2, wc = wid & 3;
    int g = lane >> 2, t4 = lane & 3;
    int region = wc >> 1;
    int kbase = region * 64;

    if (t < 128) sBias[t] = (t < 64) ? bp2[t] : bq2[t - 64];

    for (int i = t; i < 2048; i += 512) {
        int r = i >> 4, k8 = (i & 15) * 8;
        size_t goff = (size_t)(m0 + r) * 128 + k8;
        *(uint4*)(sHh + r * 136 + k8) = *(const uint4*)(g_Hh + goff);
        *(uint4*)(sHl + r * 136 + k8) = *(const uint4*)(g_Hl + goff);
    }
    for (int i = t; i < 1024; i += 512) {
        int rg = i >> 9, n = (i >> 3) & 63, k8 = (i & 7) * 8;
        size_t goff = (size_t)rg * 4096 + (size_t)n * 64 + k8;
        *(uint4*)(sWh + (rg * 64 + n) * 72 + k8) = *(const uint4*)(g_W2Th + goff);
        *(uint4*)(sWl + (rg * 64 + n) * 72 + k8) = *(const uint4*)(g_W2Tl + goff);
    }
    __syncthreads();

    float acc[2][4][4];
#pragma unroll
    for (int r = 0; r < 2; r++)
#pragma unroll
        for (int c = 0; c < 4; c++)
#pragma unroll
            for (int j = 0; j < 4; j++) acc[r][c][j] = 0.f;

#pragma unroll
    for (int pass = 0; pass < 3; pass++) {
        const __nv_bfloat16* A = (pass == 2) ? sHl : sHh;
        const __nv_bfloat16* B = (pass == 1) ? sWl : sWh;
#pragma unroll
        for (int ks = 0; ks < 4; ks++) {
            int k0 = kbase + ks * 16;
            uint32_t af[2][4];
#pragma unroll
            for (int rt = 0; rt < 2; rt++) {
                int row = wr * 32 + rt * 16;
                af[rt][0] = *(const uint32_t*)(A + (row + g) * 136 + k0 + 2 * t4);
                af[rt][1] = *(const uint32_t*)(A + (row + g + 8) * 136 + k0 + 2 * t4);
                af[rt][2] = *(const uint32_t*)(A + (row + g) * 136 + k0 + 2 * t4 + 8);
                af[rt][3] = *(const uint32_t*)(A + (row + g + 8) * 136 + k0 + 2 * t4 + 8);
            }
#pragma unroll
            for (int ct = 0; ct < 4; ct++) {
                int nl = (wc & 1) * 32 + ct * 8;
                int kk = ks * 16;
                const __nv_bfloat16* Bp = B + (region * 64 + nl + g) * 72 + kk + 2 * t4;
                uint32_t b0 = *(const uint32_t*)(Bp);
                uint32_t b1 = *(const uint32_t*)(Bp + 8);
                mma_bf16(acc[0][ct], af[0], b0, b1);
                mma_bf16(acc[1][ct], af[1], b0, b1);
            }
        }
    }

#pragma unroll
    for (int rt = 0; rt < 2; rt++) {
        int r0 = wr * 32 + rt * 16 + g;
        int r1 = r0 + 8;
        size_t m0r0 = (size_t)(m0 + r0);
        size_t m0r1 = (size_t)(m0 + r1);
#pragma unroll
        for (int ct = 0; ct < 4; ct++) {
            int nn = wc * 32 + ct * 8 + 2 * t4;
            float b0 = sBias[nn], b1 = sBias[nn + 1];
            float2 o0, o1;
            o0.x = fast_tanh(acc[rt][ct][0] + b0);
            o0.y = fast_tanh(acc[rt][ct][1] + b1);
            o1.x = fast_tanh(acc[rt][ct][2] + b0);
            o1.y = fast_tanh(acc[rt][ct][3] + b1);
            *(float2*)(g_T2 + m0r0 * 128 + nn) = o0;
            *(float2*)(g_T2 + m0r1 * 128 + nn) = o1;
        }
    }
}

// ---------------- R1: final_feature mean ----------------
__global__ void k_r1(float* __restrict__ out_ff) {
    int n = blockIdx.x, t = threadIdx.x;   // 64 threads
    float s = 0.f;
#pragma unroll 8
    for (int q = 0; q < SEQ_; q++) s += g_TA[((size_t)n * SEQ_ + q) * 64 + t];
    out_ff[n * 64 + t] = s * (1.0f / (float)SEQ_);
}

// ---------------- R2: pos/neg vec means + sq-norms + bf16 split ----------------
__global__ void k_r2() {
    __shared__ float ws[4];
    int n = blockIdx.x, t = threadIdx.x;   // 128 threads
    float s = 0.f;
#pragma unroll 8
    for (int q = 0; q < SEQ_; q++) s += g_T2[((size_t)n * SEQ_ + q) * 128 + t];
    float v = s * (1.0f / (float)SEQ_);
    __nv_bfloat16 h, l; bf16split(v, h, l);
    if (t < 64) {
        g_posvec[n * 64 + t] = v;
        g_pvh[n * 64 + t] = h; g_pvl[n * 64 + t] = l;
    } else {
        g_negvec[n * 64 + (t - 64)] = v;
        g_nvh[n * 64 + (t - 64)] = h; g_nvl[n * 64 + (t - 64)] = l;
    }
    float sq = v * v;
#pragma unroll
    for (int o = 16; o; o >>= 1) sq += __shfl_xor_sync(0xffffffffu, sq, o);
    if ((t & 31) == 0) ws[t >> 5] = sq;
    __syncthreads();
    if (t == 0) {
        g_psn[n] = ws[0] + ws[1];
        g_nsn[n] = ws[2] + ws[3];
    }
}

// ---------------- K8: similarity sums (tensor-core, manual frag loads) ----------------
#define SIM_STR 72
#define SIM_TILE (128 * SIM_STR)
#define SIMTC_SMEM (6 * SIM_TILE * 2)   // 110592 bytes
__global__ void __launch_bounds__(256)
k_sims_tc() {
    extern __shared__ __nv_bfloat16 ssm[];
    __nv_bfloat16* pIh = ssm;
    __nv_bfloat16* pIl = pIh + SIM_TILE;
    __nv_bfloat16* pJh = pIl + SIM_TILE;
    __nv_bfloat16* pJl = pJh + SIM_TILE;
    __nv_bfloat16* nJh = pJl + SIM_TILE;
    __nv_bfloat16* nJl = nJh + SIM_TILE;
    __shared__ float snI[128], snP[128], snN[128];
    __shared__ float rp[256], rn[256];

    int bi = blockIdx.y, bj = blockIdx.x, t = threadIdx.x;
    int wid = t >> 5, lane = t & 31;
    int wr = wid >> 1, wc = wid & 1;
    int g = lane >> 2, t4 = lane & 3;

    for (int i = t; i < 1024; i += 256) {
        int r = i >> 3, q = (i & 7) * 8;
        *(uint4*)(pIh + r * SIM_STR + q) = *(const uint4*)(g_pvh + (bi * 128 + r) * 64 + q);
        *(uint4*)(pIl + r * SIM_STR + q) = *(const uint4*)(g_pvl + (bi * 128 + r) * 64 + q);
        *(uint4*)(pJh + r * SIM_STR + q) = *(const uint4*)(g_pvh + (bj * 128 + r) * 64 + q);
        *(uint4*)(pJl + r * SIM_STR + q) = *(const uint4*)(g_pvl + (bj * 128 + r) * 64 + q);
        *(uint4*)(nJh + r * SIM_STR + q) = *(const uint4*)(g_nvh + (bj * 128 + r) * 64 + q);
        *(uint4*)(nJl + r * SIM_STR + q) = *(const uint4*)(g_nvl + (bj * 128 + r) * 64 + q);
    }
    if (t < 128) { snI[t] = g_psn[bi * 128 + t]; snN[t] = g_nsn[bj * 128 + t]; }
    else snP[t - 128] = g_psn[bj * 128 + (t - 128)];
    __syncthreads();

    float lp = 0.f, ln = 0.f;
#pragma unroll
    for (int targ = 0; targ < 2; targ++) {
        const __nv_bfloat16* Bh = targ ? nJh : pJh;
        const __nv_bfloat16* Bl = targ ? nJl : pJl;
        float acc[2][8][4];
#pragma unroll
        for (int r = 0; r < 2; r++)
#pragma unroll
            for (int c = 0; c < 8; c++)
#pragma unroll
                for (int j = 0; j < 4; j++) acc[r][c][j] = 0.f;

#pragma unroll
        for (int pass = 0; pass < 3; pass++) {
            const __nv_bfloat16* A = (pass == 2) ? pIl : pIh;
            const __nv_bfloat16* B = (pass == 1) ? Bl : Bh;
#pragma unroll
            for (int ks = 0; ks < 4; ks++) {
                int k0 = ks * 16;
                uint32_t af[2][4];
#pragma unroll
                for (int rt = 0; rt < 2; rt++) {
                    int row = wr * 32 + rt * 16;
                    af[rt][0] = *(const uint32_t*)(A + (row + g) * SIM_STR + k0 + 2 * t4);
                    af[rt][1] = *(const uint32_t*)(A + (row + g + 8) * SIM_STR + k0 + 2 * t4);
                    af[rt][2] = *(const uint32_t*)(A + (row + g) * SIM_STR + k0 + 2 * t4 + 8);
                    af[rt][3] = *(const uint32_t*)(A + (row + g + 8) * SIM_STR + k0 + 2 * t4 + 8);
                }
#pragma unroll
                for (int ct = 0; ct < 8; ct++) {
                    int n = wc * 64 + ct * 8;
                    uint32_t b0 = *(const uint32_t*)(B + (n + g) * SIM_STR + k0 + 2 * t4);
                    uint32_t b1 = *(const uint32_t*)(B + (n + g) * SIM_STR + k0 + 2 * t4 + 8);
                    mma_bf16(acc[0][ct], af[0], b0, b1);
                    mma_bf16(acc[1][ct], af[1], b0, b1);
                }
            }
        }

        const float* snX = targ ? snN : snP;
        float tot = 0.f;
#pragma unroll
        for (int rt = 0; rt < 2; rt++) {
#pragma unroll
            for (int ct = 0; ct < 8; ct++) {
                int rl = wr * 32 + rt * 16 + g;
                int cl = wc * 64 + ct * 8 + 2 * t4;
                float nI0 = snI[rl], nI1 = snI[rl + 8];
                float c0 = snX[cl], c1 = snX[cl + 1];
                float sqv[4] = { nI0 + c0 - 2.f * acc[rt][ct][0],
                                 nI0 + c1 - 2.f * acc[rt][ct][1],
                                 nI1 + c0 - 2.f * acc[rt][ct][2],
                                 nI1 + c1 - 2.f * acc[rt][ct][3] };
#pragma unroll
                for (int j = 0; j < 4; j++) {
                    float sq = fmaxf(sqv[j], 0.0f);
                    float d = (sq > 0.0f) ? sqrtf(sq) : 0.0f;
                    tot += __expf(-d);
                }
            }
        }
        if (targ == 0) lp = tot; else ln = tot;
    }
    rp[t] = lp; rn[t] = ln;
    __syncthreads();
    for (int o = 128; o; o >>= 1) {
        if (t < o) { rp[t] += rp[t + o]; rn[t] += rn[t + o]; }
        __syncthreads();
    }
    if (t == 0) {
        int bid = bi * 32 + bj;
        g_sp[bid] = rp[0]; g_sn[bid] = rn[0];
    }
}

__global__ void k_loss(float* __restrict__ out_loss) {
    __shared__ float rp[1024], rn[1024];
    int t = threadIdx.x;
    rp[t] = g_sp[t]; rn[t] = g_sn[t];
    __syncthreads();
    for (int o = 512; o; o >>= 1) {
        if (t < o) { rp[t] += rp[t + o]; rn[t] += rn[t + o]; }
        __syncthreads();
    }
    if (t == 0) out_loss[0] = -logf(rp[0] / rn[0]);
}

// ---------------- launch ----------------
extern "C" void kernel_launch(void* const* d_in, const int* in_sizes, int n_in,
                              void* d_out, int out_size) {
    const float* A     = (const float*)d_in[0];
    const int*   C     = (const int*)d_in[1];
    const float* L     = (const float*)d_in[2];
    const float* W1    = (const float*)d_in[3];
    const float* b1    = (const float*)d_in[4];
    const float* gam   = (const float*)d_in[5];
    const float* bet   = (const float*)d_in[6];
    const float* sig   = (const float*)d_in[7];
    const float* Pw    = (const float*)d_in[8];
    const float* Nw    = (const float*)d_in[9];
    const float* Wp1   = (const float*)d_in[10];
    const float* bp1   = (const float*)d_in[11];
    const float* Wp2   = (const float*)d_in[12];
    const float* bp2   = (const float*)d_in[13];
    const float* Wq1   = (const float*)d_in[14];
    const float* bq1   = (const float*)d_in[15];
    const float* Wq2   = (const float*)d_in[16];
    const float* bq2   = (const float*)d_in[17];
    const float* Wa    = (const float*)d_in[18];
    const float* ba    = (const float*)d_in[19];

    float* out = (float*)d_out;
    float* out_ff   = out;                    // [4096*64]
    float* out_loss = out + N_ * RED_;        // [1]
    float* out_D    = out + N_ * RED_ + 1;    // [4096*4096], only 4B-aligned!

    cudaFuncSetAttribute(k_gemm1_mma, cudaFuncAttributeMaxDynamicSharedMemorySize, G1_SMEM);
    cudaFuncSetAttribute(k_gemm2_mma, cudaFuncAttributeMaxDynamicSharedMemorySize, G2_SMEM);
    cudaFuncSetAttribute(k_sims_tc, cudaFuncAttributeMaxDynamicSharedMemorySize, SIMTC_SMEM);
    cudaFuncSetAttribute(k_dstats_tf32, cudaFuncAttributeMaxDynamicSharedMemorySize, DT_SMEM);

    k_wsplit<<<192, 256>>>(Wp1, Wq1, Wa, Wp2, Wq2);
    k_gather_h<<<N_, 128>>>(A, C, W1, b1);
    k_bnstats<<<1, 1024>>>();
    k_emb<<<512, 256>>>(gam, bet);
    k_dstats_tf32<<<dim3(32, 32), 256, DT_SMEM>>>(sig);
    k_dconsts<<<1, 1024>>>();
    k_dfinal<<<(N_ * (N_ / 4)) / 256, 256>>>(out_D);
    k_gemm1_mma<<<M1_ / 128, 512, G1_SMEM>>>(L, Pw, Nw, C, bp1, bq1, ba);
    k_gemm2_mma<<<M1_ / 128, 512, G2_SMEM>>>(bp2, bq2);
    k_r1<<<N_, 64>>>(out_ff);
    k_r2<<<N_, 128>>>();
    k_sims_tc<<<dim3(32, 32), 256, SIMTC_SMEM>>>();
    k_loss<<<1, 1024>>>(out_loss);
}

// round 16
// speedup vs baseline: 1.6665x; 1.0231x over previous
#include <cuda_runtime.h>
#include <cuda_bf16.h>
#include <math.h>
#include <stdint.h>

#define N_   4096
#define SEQ_ 41
#define VEC_ 15
#define T_   8
#define EMB_ 32
#define LDIM_ 256
#define RED_ 64
#define M1_  (N_ * SEQ_)   // 167936 rows = 1312 tiles of 128

// ---------------- scratch (device globals; no allocation) ----------------
__device__ float g_h[N_ * EMB_];
__device__ float g_emb[N_ * EMB_];
__device__ float g_sqn[N_];
__device__ float g_mu[EMB_];
__device__ float g_rstd[EMB_];
__device__ float g_psum[1024];
__device__ float g_pmin[1024];
__device__ float g_pmax[1024];
__device__ float g_dc[3];
__device__ float g_posvec[N_ * RED_];
__device__ float g_negvec[N_ * RED_];
__device__ float g_psn[N_];
__device__ float g_nsn[N_];
__device__ float g_TA[(size_t)M1_ * 64];
__device__ float g_T2[(size_t)M1_ * 128];
__device__ float g_Draw[(size_t)N_ * N_];
__device__ float g_sp[1024];
__device__ float g_sn[1024];
// bf16-split intermediates
__device__ __nv_bfloat16 g_Hh[(size_t)M1_ * 128];
__device__ __nv_bfloat16 g_Hl[(size_t)M1_ * 128];
__device__ __nv_bfloat16 g_W1Th[3 * 64 * 256];
__device__ __nv_bfloat16 g_W1Tl[3 * 64 * 256];
__device__ __nv_bfloat16 g_W2Th[2 * 64 * 64];
__device__ __nv_bfloat16 g_W2Tl[2 * 64 * 64];
__device__ __nv_bfloat16 g_pvh[N_ * 64], g_pvl[N_ * 64];
__device__ __nv_bfloat16 g_nvh[N_ * 64], g_nvl[N_ * 64];

__device__ __forceinline__ float fast_tanh(float x) {
    float e = __expf(2.0f * x);
    return 1.0f - 2.0f / (e + 1.0f);
}
// Zero-MUFU tanh: Pade(7,6) rational + bit-trick Newton reciprocal, clamp to [-1,1].
// Max abs error ~9e-5 (near |x|~5); pure FMA/ALU pipe — frees MUFU for exp/sqrt kernels.
__device__ __forceinline__ float fmatanh(float x) {
    float x2 = x * x;
    float num = fmaf(x2, fmaf(x2, fmaf(x2, 1.0f, 378.0f), 17325.0f), 135135.0f) * x;
    float den = fmaf(x2, fmaf(x2, fmaf(x2, 28.0f, 3150.0f), 62370.0f), 135135.0f);
    // reciprocal of den (den >= 135135 > 0): bit-trick seed + 3 Newton steps
    float r = __uint_as_float(0x7EF311C3u - __float_as_uint(den));
    r = r * fmaf(-den, r, 2.0f);
    r = r * fmaf(-den, r, 2.0f);
    r = r * fmaf(-den, r, 2.0f);
    float t = num * r;
    return fminf(fmaxf(t, -1.0f), 1.0f);
}
__device__ __forceinline__ void bf16split(float x, __nv_bfloat16& h, __nv_bfloat16& l) {
    h = __float2bfloat16(x);
    l = __float2bfloat16(x - __bfloat162float(h));
}
__device__ __forceinline__ unsigned packbf2(__nv_bfloat16 a, __nv_bfloat16 b) {
    __nv_bfloat162 t = __nv_bfloat162(a, b);
    return *reinterpret_cast<unsigned*>(&t);
}
__device__ __forceinline__ float tf32_round(float x) {
    float r;
    asm("cvt.rna.tf32.f32 %0, %1;" : "=f"(r) : "f"(x));
    return r;
}

// bf16 warp MMA: D(16x8,f32) += A(16x16,row) * B(16x8,col)
__device__ __forceinline__ void mma_bf16(float c[4], const uint32_t a[4],
                                         uint32_t b0, uint32_t b1) {
    asm volatile(
        "mma.sync.aligned.m16n8k16.row.col.f32.bf16.bf16.f32 "
        "{%0,%1,%2,%3}, {%4,%5,%6,%7}, {%8,%9}, {%0,%1,%2,%3};"
        : "+f"(c[0]), "+f"(c[1]), "+f"(c[2]), "+f"(c[3])
        : "r"(a[0]), "r"(a[1]), "r"(a[2]), "r"(a[3]), "r"(b0), "r"(b1));
}
// tf32 warp MMA: D(16x8,f32) += A(16x8,row) * B(8x8,col)
__device__ __forceinline__ void mma_tf32(float c[4], const uint32_t a[4],
                                         uint32_t b0, uint32_t b1) {
    asm volatile(
        "mma.sync.aligned.m16n8k8.row.col.f32.tf32.tf32.f32 "
        "{%0,%1,%2,%3}, {%4,%5,%6,%7}, {%8,%9}, {%0,%1,%2,%3};"
        : "+f"(c[0]), "+f"(c[1]), "+f"(c[2]), "+f"(c[3])
        : "r"(a[0]), "r"(a[1]), "r"(a[2]), "r"(a[3]), "r"(b0), "r"(b1));
}

// ---------------- K1: gather + interp + h = tanh(flat@W1 + b1) ----------------
__global__ void k_gather_h(const float* __restrict__ A, const int* __restrict__ C,
                           const float* __restrict__ W1, const float* __restrict__ b1) {
    __shared__ float flat[120];
    int n = blockIdx.x;
    int t = threadIdx.x;
    int start = C[2 * n], end = C[2 * n + 1];
    int len = end - start + 1;
    if (t < 120) {
        int j = t / VEC_, v = t % VEC_;
        float scale = (float)len / (float)T_;
        float src = fmaxf(scale * ((float)j + 0.5f) - 0.5f, 0.0f);
        int i0 = min((int)floorf(src), len - 1);
        int i1 = min(i0 + 1, len - 1);
        float w = src - (float)i0;
        const float* Ar = A + (size_t)n * SEQ_ * VEC_;
        float g0 = Ar[(start + i0) * VEC_ + v];
        float g1 = Ar[(start + i1) * VEC_ + v];
        flat[t] = (1.0f - w) * g0 + w * g1;
    }
    __syncthreads();
    if (t < 32) {
        float acc = b1[t];
#pragma unroll
        for (int k = 0; k < 120; k++) acc += flat[k] * W1[k * 32 + t];
        g_h[n * 32 + t] = tanhf(acc);
    }
}

// ---------------- K2: batchnorm stats ----------------
__global__ void k_bnstats() {
    __shared__ float ssum[32][33];
    __shared__ float ssq[32][33];
    int c = threadIdx.x & 31, g = threadIdx.x >> 5;
    float s = 0.f, q = 0.f;
    for (int n = g; n < N_; n += 32) {
        float v = g_h[n * 32 + c];
        s += v; q += v * v;
    }
    ssum[g][c] = s; ssq[g][c] = q;
    __syncthreads();
    if (threadIdx.x < 32) {
        float S = 0.f, Q = 0.f;
        for (int gg = 0; gg < 32; gg++) { S += ssum[gg][threadIdx.x]; Q += ssq[gg][threadIdx.x]; }
        float mu = S / (float)N_;
        float var = Q / (float)N_ - mu * mu;
        g_mu[threadIdx.x] = mu;
        g_rstd[threadIdx.x] = rsqrtf(var + 1e-5f);
    }
}

// ---------------- K3: emb + row sq-norms ----------------
__global__ void k_emb(const float* __restrict__ gamma, const float* __restrict__ beta) {
    int idx = blockIdx.x * 256 + threadIdx.x;
    int c = idx & 31;
    float e = gamma[c] * (g_h[idx] - g_mu[c]) * g_rstd[c] + beta[c];
    g_emb[idx] = e;
    float sq = e * e;
#pragma unroll
    for (int o = 16; o; o >>= 1) sq += __shfl_xor_sync(0xffffffffu, sq, o);
    if (c == 0) g_sqn[idx >> 5] = sq;
}

// ---------------- K4: D stats (tf32 3-pass split tensor-core GEMM) ----------------
#define DT_STR 36
#define DT_SMEM (4 * 128 * DT_STR * 4)   // 73728 bytes
__global__ void __launch_bounds__(256)
k_dstats_tf32(const float* __restrict__ sigma_p) {
    extern __shared__ float dsf[];
    float* sIh = dsf;
    float* sIl = sIh + 128 * DT_STR;
    float* sJh = sIl + 128 * DT_STR;
    float* sJl = sJh + 128 * DT_STR;
    __shared__ float snI[128], snJ[128];
    __shared__ float rs[256], rmn[256], rmx[256];

    int bi = blockIdx.y, bj = blockIdx.x, t = threadIdx.x;
    int wid = t >> 5, lane = t & 31;
    int wr = wid >> 1, wc = wid & 1;
    int g = lane >> 2, t4 = lane & 3;

    for (int i = t; i < 128 * 32; i += 256) {
        int r = i >> 5, k = i & 31;
        float eI = g_emb[(bi * 128 + r) * 32 + k];
        float eJ = g_emb[(bj * 128 + r) * 32 + k];
        float hI = tf32_round(eI), hJ = tf32_round(eJ);
        sIh[r * DT_STR + k] = hI; sIl[r * DT_STR + k] = tf32_round(eI - hI);
        sJh[r * DT_STR + k] = hJ; sJl[r * DT_STR + k] = tf32_round(eJ - hJ);
    }
    if (t < 128) snI[t] = g_sqn[bi * 128 + t];
    else snJ[t - 128] = g_sqn[bj * 128 + (t - 128)];
    __syncthreads();

    float acc[2][8][4];
#pragma unroll
    for (int r = 0; r < 2; r++)
#pragma unroll
        for (int c = 0; c < 8; c++)
#pragma unroll
            for (int j = 0; j < 4; j++) acc[r][c][j] = 0.f;

#pragma unroll
    for (int pass = 0; pass < 3; pass++) {
        const float* A = (pass == 2) ? sIl : sIh;
        const float* B = (pass == 1) ? sJl : sJh;
#pragma unroll
        for (int ks = 0; ks < 4; ks++) {
            int k0 = ks * 8;
            uint32_t af[2][4];
#pragma unroll
            for (int rt = 0; rt < 2; rt++) {
                int row = wr * 32 + rt * 16;
                af[rt][0] = __float_as_uint(A[(row + g) * DT_STR + k0 + t4]);
                af[rt][1] = __float_as_uint(A[(row + g + 8) * DT_STR + k0 + t4]);
                af[rt][2] = __float_as_uint(A[(row + g) * DT_STR + k0 + t4 + 4]);
                af[rt][3] = __float_as_uint(A[(row + g + 8) * DT_STR + k0 + t4 + 4]);
            }
#pragma unroll
            for (int ct = 0; ct < 8; ct++) {
                int n = wc * 64 + ct * 8;
                uint32_t b0 = __float_as_uint(B[(n + g) * DT_STR + k0 + t4]);
                uint32_t b1 = __float_as_uint(B[(n + g) * DT_STR + k0 + t4 + 4]);
                mma_tf32(acc[0][ct], af[0], b0, b1);
                mma_tf32(acc[1][ct], af[1], b0, b1);
            }
        }
    }

    float inv2s;
    { float sg = sigma_p[0]; inv2s = 0.5f / (sg * sg); }
    float lsum = 0.f, lmin = 3.4e38f, lmax = -3.4e38f;
#pragma unroll
    for (int rt = 0; rt < 2; rt++) {
#pragma unroll
        for (int ct = 0; ct < 8; ct++) {
            int rl0 = wr * 32 + rt * 16 + g;
            int cl = wc * 64 + ct * 8 + 2 * t4;
            int gi0 = bi * 128 + rl0, gi1 = gi0 + 8;
            int gj0 = bj * 128 + cl, gj1 = gj0 + 1;
            float nI0 = snI[rl0], nI1 = snI[rl0 + 8];
            float nJ0 = snJ[cl], nJ1 = snJ[cl + 1];
            float v[4];
            float sqv[4] = { nI0 + nJ0 - 2.f * acc[rt][ct][0],
                             nI0 + nJ1 - 2.f * acc[rt][ct][1],
                             nI1 + nJ0 - 2.f * acc[rt][ct][2],
                             nI1 + nJ1 - 2.f * acc[rt][ct][3] };
#pragma unroll
            for (int j = 0; j < 4; j++) {
                float sq = fmaxf(sqv[j], 0.0f);
                float d = (sq > 0.0f) ? sqrtf(sq) : 0.0f;
                v[j] = __expf(-d * inv2s);
            }
            *(float2*)(g_Draw + (size_t)gi0 * N_ + gj0) = make_float2(v[0], v[1]);
            *(float2*)(g_Draw + (size_t)gi1 * N_ + gj0) = make_float2(v[2], v[3]);
            int gis[4] = { gi0, gi0, gi1, gi1 };
            int gjs[4] = { gj0, gj1, gj0, gj1 };
#pragma unroll
            for (int j = 0; j < 4; j++) {
                if (gis[j] != gjs[j]) {
                    lsum += v[j];
                    lmin = fminf(lmin, v[j]);
                    lmax = fmaxf(lmax, v[j]);
                }
            }
        }
    }
    rs[t] = lsum; rmn[t] = lmin; rmx[t] = lmax;
    __syncthreads();
    for (int o = 128; o; o >>= 1) {
        if (t < o) {
            rs[t] += rs[t + o];
            rmn[t] = fminf(rmn[t], rmn[t + o]);
            rmx[t] = fmaxf(rmx[t], rmx[t + o]);
        }
        __syncthreads();
    }
    if (t == 0) {
        int bid = bi * 32 + bj;
        g_psum[bid] = rs[0]; g_pmin[bid] = rmn[0]; g_pmax[bid] = rmx[0];
    }
}

__global__ void k_dconsts() {
    __shared__ float rs[1024], rmn[1024], rmx[1024];
    int t = threadIdx.x;
    rs[t] = g_psum[t]; rmn[t] = g_pmin[t]; rmx[t] = g_pmax[t];
    __syncthreads();
    for (int o = 512; o; o >>= 1) {
        if (t < o) {
            rs[t] += rs[t + o];
            rmn[t] = fminf(rmn[t], rmn[t + o]);
            rmx[t] = fmaxf(rmx[t], rmx[t + o]);
        }
        __syncthreads();
    }
    if (t == 0) {
        float avg = rs[0] / ((float)N_ * (float)(N_ - 1));
        float mn = (rmn[0] < avg) ? 0.0f : rmn[0];
        float mx = rmx[0];
        if (mx == mn) mx = mn + 1.0f;
        g_dc[0] = avg; g_dc[1] = mn; g_dc[2] = 1.0f / (mx - mn);
    }
}

// D finalize: output pointer only 4B-aligned -> scalar stores
__global__ void k_dfinal(float* __restrict__ D) {
    float avg = g_dc[0], mn = g_dc[1], inv = g_dc[2];
    size_t base = ((size_t)blockIdx.x * 256 + threadIdx.x) * 4;
    float4 v = *(const float4*)(g_Draw + base);
    float vv[4] = { v.x, v.y, v.z, v.w };
#pragma unroll
    for (int j = 0; j < 4; j++) {
        size_t idx = base + j;
        int gi = (int)(idx >> 12);
        int gj = (int)(idx & 4095);
        float dt = (vv[j] < avg) ? 0.0f : vv[j];
        D[idx] = (gi == gj) ? 1.0f : (dt - mn) * inv;
    }
}

// ---------------- W split/transpose precompute ----------------
__global__ void k_wsplit(const float* __restrict__ Wp1, const float* __restrict__ Wq1,
                         const float* __restrict__ Wa,
                         const float* __restrict__ Wp2, const float* __restrict__ Wq2) {
    int idx = blockIdx.x * 256 + threadIdx.x;
    if (idx < 3 * 64 * 256) {
        int w = idx >> 14;
        int n = (idx >> 8) & 63;
        int k = idx & 255;
        const float* W = (w == 0) ? Wp1 : (w == 1) ? Wq1 : Wa;
        float x = W[k * 64 + n];
        __nv_bfloat16 h, l; bf16split(x, h, l);
        g_W1Th[idx] = h; g_W1Tl[idx] = l;
    }
    if (idx < 2 * 64 * 64) {
        int p = idx >> 12;
        int n = (idx >> 6) & 63;
        int k = idx & 63;
        const float* W = p ? Wq2 : Wp2;
        float x = W[k * 64 + n];
        __nv_bfloat16 h, l; bf16split(x, h, l);
        g_W2Th[idx] = h; g_W2Tl[idx] = l;
    }
}

// ---------------- GEMM1 (mma.sync bf16, manual frag loads + A-prefetch) ----------------
#define G1_A_ELEM (128 * 72)
#define G1_B_ELEM (192 * 72)
#define G1_SMEM ((2 * G1_A_ELEM + 2 * G1_B_ELEM) * 2)

__global__ void __launch_bounds__(512)
k_gemm1_mma(const float* __restrict__ L, const float* __restrict__ Pw,
            const float* __restrict__ Nw, const int* __restrict__ C,
            const float* __restrict__ bp1, const float* __restrict__ bq1,
            const float* __restrict__ ba) {
    extern __shared__ __nv_bfloat16 sm1[];
    __nv_bfloat16* sAh = sm1;
    __nv_bfloat16* sAl = sAh + G1_A_ELEM;
    __nv_bfloat16* sBh = sAl + G1_A_ELEM;
    __nv_bfloat16* sBl = sBh + G1_B_ELEM;
    __shared__ float sMp[128], sMn[128], sBias[192];

    int t = threadIdx.x;
    int m0 = blockIdx.x * 128;
    int wid = t >> 5, lane = t & 31;
    int wr = wid >> 2, wc = wid & 3;        // 4x4 warps
    int g = lane >> 2, t4 = lane & 3;

    if (t < 128) {
        int m = m0 + t;
        int n = m / SEQ_, s = m - n * SEQ_;
        int st = C[2 * n], en = C[2 * n + 1];
        bool in = (s >= st && s <= en);
        sMp[t] = in ? Pw[n * SEQ_ + s] : 0.0f;
        sMn[t] = in ? 0.0f : Nw[n * SEQ_ + s];
    } else if (t < 320) {
        int c = t - 128;
        sBias[c] = (c < 64) ? bp1[c] : (c < 128) ? bq1[c - 64] : ba[c - 128];
    }

    float acc[2][6][4];
#pragma unroll
    for (int r = 0; r < 2; r++)
#pragma unroll
        for (int c = 0; c < 6; c++)
#pragma unroll
            for (int j = 0; j < 4; j++) acc[r][c][j] = 0.f;

    // A-chunk prefetch registers (chunk 0)
    int pr_r = t >> 4, pr_k4 = (t & 15) * 4;   // each thread owns rows pr_r + i*32
    float4 pre[4];
#pragma unroll
    for (int i = 0; i < 4; i++) {
        int r = pr_r + i * 32;
        pre[i] = *(const float4*)(L + (size_t)(m0 + r) * 256 + pr_k4);
    }

    for (int kc = 0; kc < 4; kc++) {
        __syncthreads();
        // store prefetched A chunk (split fp32 -> hi/lo bf16)
#pragma unroll
        for (int i = 0; i < 4; i++) {
            int r = pr_r + i * 32;
            float xs[4] = { pre[i].x, pre[i].y, pre[i].z, pre[i].w };
            __nv_bfloat16 h[4], l[4];
#pragma unroll
            for (int j = 0; j < 4; j++) bf16split(xs[j], h[j], l[j]);
            uint2 uh = { packbf2(h[0], h[1]), packbf2(h[2], h[3]) };
            uint2 ul = { packbf2(l[0], l[1]), packbf2(l[2], l[3]) };
            *(uint2*)(sAh + r * 72 + pr_k4) = uh;
            *(uint2*)(sAl + r * 72 + pr_k4) = ul;
        }
        // B stage (L2-hot weights)
        for (int i = t; i < 1536; i += 512) {
            int n = i >> 3, k8 = (i & 7) * 8;
            size_t goff = (size_t)(n >> 6) * 16384 + (size_t)(n & 63) * 256 + kc * 64 + k8;
            *(uint4*)(sBh + n * 72 + k8) = *(const uint4*)(g_W1Th + goff);
            *(uint4*)(sBl + n * 72 + k8) = *(const uint4*)(g_W1Tl + goff);
        }
        __syncthreads();
        // prefetch next A chunk — retires under the MMA section below
        if (kc < 3) {
#pragma unroll
            for (int i = 0; i < 4; i++) {
                int r = pr_r + i * 32;
                pre[i] = *(const float4*)(L + (size_t)(m0 + r) * 256 + (kc + 1) * 64 + pr_k4);
            }
        }

#pragma unroll
        for (int pass = 0; pass < 3; pass++) {
            const __nv_bfloat16* A = (pass == 2) ? sAl : sAh;
            const __nv_bfloat16* B = (pass == 1) ? sBl : sBh;
#pragma unroll
            for (int ks = 0; ks < 4; ks++) {
                int k0 = ks * 16;
                uint32_t af[2][4];
#pragma unroll
                for (int rt = 0; rt < 2; rt++) {
                    int row = wr * 32 + rt * 16;
                    af[rt][0] = *(const uint32_t*)(A + (row + g) * 72 + k0 + 2 * t4);
                    af[rt][1] = *(const uint32_t*)(A + (row + g + 8) * 72 + k0 + 2 * t4);
                    af[rt][2] = *(const uint32_t*)(A + (row + g) * 72 + k0 + 2 * t4 + 8);
                    af[rt][3] = *(const uint32_t*)(A + (row + g + 8) * 72 + k0 + 2 * t4 + 8);
                }
#pragma unroll
                for (int ct = 0; ct < 6; ct++) {
                    int n = wc * 48 + ct * 8;
                    uint32_t b0 = *(const uint32_t*)(B + (n + g) * 72 + k0 + 2 * t4);
                    uint32_t b1 = *(const uint32_t*)(B + (n + g) * 72 + k0 + 2 * t4 + 8);
                    mma_bf16(acc[0][ct], af[0], b0, b1);
                    mma_bf16(acc[1][ct], af[1], b0, b1);
                }
            }
        }
    }

#pragma unroll
    for (int rt = 0; rt < 2; rt++) {
        int r0 = wr * 32 + rt * 16 + g;
        int r1 = r0 + 8;
        size_t m0r0 = (size_t)(m0 + r0);
        size_t m0r1 = (size_t)(m0 + r1);
        float mp0 = sMp[r0], mn0 = sMn[r0];
        float mp1 = sMp[r1], mn1 = sMn[r1];
#pragma unroll
        for (int ct = 0; ct < 6; ct++) {
            int nn = wc * 48 + ct * 8 + 2 * t4;
            float b0 = sBias[nn], b1 = sBias[nn + 1];
            if (nn < 128) {
                float s0 = (nn < 64) ? mp0 : mn0;
                float s1 = (nn < 64) ? mp1 : mn1;
                float h00 = fmatanh(s0 * acc[rt][ct][0] + b0);
                float h01 = fmatanh(s0 * acc[rt][ct][1] + b1);
                float h10 = fmatanh(s1 * acc[rt][ct][2] + b0);
                float h11 = fmatanh(s1 * acc[rt][ct][3] + b1);
                __nv_bfloat16 hh, hl, h2h, h2l;
                bf16split(h00, hh, hl); bf16split(h01, h2h, h2l);
                *(unsigned*)(&g_Hh[m0r0 * 128 + nn]) = packbf2(hh, h2h);
                *(unsigned*)(&g_Hl[m0r0 * 128 + nn]) = packbf2(hl, h2l);
                bf16split(h10, hh, hl); bf16split(h11, h2h, h2l);
                *(unsigned*)(&g_Hh[m0r1 * 128 + nn]) = packbf2(hh, h2h);
                *(unsigned*)(&g_Hl[m0r1 * 128 + nn]) = packbf2(hl, h2l);
            } else {
                int na = nn - 128;
                float s0 = mp0 + mn0, s1 = mp1 + mn1;
                float2 o0, o1;
                o0.x = fmatanh(s0 * acc[rt][ct][0] + b0);
                o0.y = fmatanh(s0 * acc[rt][ct][1] + b1);
                o1.x = fmatanh(s1 * acc[rt][ct][2] + b0);
                o1.y = fmatanh(s1 * acc[rt][ct][3] + b1);
                *(float2*)(g_TA + m0r0 * 64 + na) = o0;
                *(float2*)(g_TA + m0r1 * 64 + na) = o1;
            }
        }
    }
}

// ---------------- GEMM2 (mma.sync bf16, manual frag loads) ----------------
#define G2_H_ELEM (128 * 136)
#define G2_W_ELEM (2 * 64 * 72)
#define G2_SMEM ((2 * G2_H_ELEM + 2 * G2_W_ELEM) * 2)

__global__ void __launch_bounds__(512)
k_gemm2_mma(const float* __restrict__ bp2, const float* __restrict__ bq2) {
    extern __shared__ __nv_bfloat16 sm2[];
    __nv_bfloat16* sHh = sm2;
    __nv_bfloat16* sHl = sHh + G2_H_ELEM;
    __nv_bfloat16* sWh = sHl + G2_H_ELEM;
    __nv_bfloat16* sWl = sWh + G2_W_ELEM;
    __shared__ float sBias[128];

    int t = threadIdx.x;
    int m0 = blockIdx.x * 128;
    int wid = t >> 5, lane = t & 31;
    int wr = wid >> 2, wc = wid & 3;
    int g = lane >> 2, t4 = lane & 3;
    int region = wc >> 1;
    int kbase = region * 64;

    if (t < 128) sBias[t] = (t < 64) ? bp2[t] : bq2[t - 64];

    for (int i = t; i < 2048; i += 512) {
        int r = i >> 4, k8 = (i & 15) * 8;
        size_t goff = (size_t)(m0 + r) * 128 + k8;
        *(uint4*)(sHh + r * 136 + k8) = *(const uint4*)(g_Hh + goff);
        *(uint4*)(sHl + r * 136 + k8) = *(const uint4*)(g_Hl + goff);
    }
    for (int i = t; i < 1024; i += 512) {
        int rg = i >> 9, n = (i >> 3) & 63, k8 = (i & 7) * 8;
        size_t goff = (size_t)rg * 4096 + (size_t)n * 64 + k8;
        *(uint4*)(sWh + (rg * 64 + n) * 72 + k8) = *(const uint4*)(g_W2Th + goff);
        *(uint4*)(sWl + (rg * 64 + n) * 72 + k8) = *(const uint4*)(g_W2Tl + goff);
    }
    __syncthreads();

    float acc[2][4][4];
#pragma unroll
    for (int r = 0; r < 2; r++)
#pragma unroll
        for (int c = 0; c < 4; c++)
#pragma unroll
            for (int j = 0; j < 4; j++) acc[r][c][j] = 0.f;

#pragma unroll
    for (int pass = 0; pass < 3; pass++) {
        const __nv_bfloat16* A = (pass == 2) ? sHl : sHh;
        const __nv_bfloat16* B = (pass == 1) ? sWl : sWh;
#pragma unroll
        for (int ks = 0; ks < 4; ks++) {
            int k0 = kbase + ks * 16;
            uint32_t af[2][4];
#pragma unroll
            for (int rt = 0; rt < 2; rt++) {
                int row = wr * 32 + rt * 16;
                af[rt][0] = *(const uint32_t*)(A + (row + g) * 136 + k0 + 2 * t4);
                af[rt][1] = *(const uint32_t*)(A + (row + g + 8) * 136 + k0 + 2 * t4);
                af[rt][2] = *(const uint32_t*)(A + (row + g) * 136 + k0 + 2 * t4 + 8);
                af[rt][3] = *(const uint32_t*)(A + (row + g + 8) * 136 + k0 + 2 * t4 + 8);
            }
#pragma unroll
            for (int ct = 0; ct < 4; ct++) {
                int nl = (wc & 1) * 32 + ct * 8;
                int kk = ks * 16;
                const __nv_bfloat16* Bp = B + (region * 64 + nl + g) * 72 + kk + 2 * t4;
                uint32_t b0 = *(const uint32_t*)(Bp);
                uint32_t b1 = *(const uint32_t*)(Bp + 8);
                mma_bf16(acc[0][ct], af[0], b0, b1);
                mma_bf16(acc[1][ct], af[1], b0, b1);
            }
        }
    }

#pragma unroll
    for (int rt = 0; rt < 2; rt++) {
        int r0 = wr * 32 + rt * 16 + g;
        int r1 = r0 + 8;
        size_t m0r0 = (size_t)(m0 + r0);
        size_t m0r1 = (size_t)(m0 + r1);
#pragma unroll
        for (int ct = 0; ct < 4; ct++) {
            int nn = wc * 32 + ct * 8 + 2 * t4;
            float b0 = sBias[nn], b1 = sBias[nn + 1];
            float2 o0, o1;
            o0.x = fmatanh(acc[rt][ct][0] + b0);
            o0.y = fmatanh(acc[rt][ct][1] + b1);
            o1.x = fmatanh(acc[rt][ct][2] + b0);
            o1.y = fmatanh(acc[rt][ct][3] + b1);
            *(float2*)(g_T2 + m0r0 * 128 + nn) = o0;
            *(float2*)(g_T2 + m0r1 * 128 + nn) = o1;
        }
    }
}

// ---------------- R1: final_feature mean ----------------
__global__ void k_r1(float* __restrict__ out_ff) {
    int n = blockIdx.x, t = threadIdx.x;   // 64 threads
    float s = 0.f;
#pragma unroll 8
    for (int q = 0; q < SEQ_; q++) s += g_TA[((size_t)n * SEQ_ + q) * 64 + t];
    out_ff[n * 64 + t] = s * (1.0f / (float)SEQ_);
}

// ---------------- R2: pos/neg vec means + sq-norms + bf16 split ----------------
__global__ void k_r2() {
    __shared__ float ws[4];
    int n = blockIdx.x, t = threadIdx.x;   // 128 threads
    float s = 0.f;
#pragma unroll 8
    for (int q = 0; q < SEQ_; q++) s += g_T2[((size_t)n * SEQ_ + q) * 128 + t];
    float v = s * (1.0f / (float)SEQ_);
    __nv_bfloat16 h, l; bf16split(v, h, l);
    if (t < 64) {
        g_posvec[n * 64 + t] = v;
        g_pvh[n * 64 + t] = h; g_pvl[n * 64 + t] = l;
    } else {
        g_negvec[n * 64 + (t - 64)] = v;
        g_nvh[n * 64 + (t - 64)] = h; g_nvl[n * 64 + (t - 64)] = l;
    }
    float sq = v * v;
#pragma unroll
    for (int o = 16; o; o >>= 1) sq += __shfl_xor_sync(0xffffffffu, sq, o);
    if ((t & 31) == 0) ws[t >> 5] = sq;
    __syncthreads();
    if (t == 0) {
        g_psn[n] = ws[0] + ws[1];
        g_nsn[n] = ws[2] + ws[3];
    }
}

// ---------------- K8: similarity sums (tensor-core, manual frag loads) ----------------
#define SIM_STR 72
#define SIM_TILE (128 * SIM_STR)
#define SIMTC_SMEM (6 * SIM_TILE * 2)   // 110592 bytes
__global__ void __launch_bounds__(256)
k_sims_tc() {
    extern __shared__ __nv_bfloat16 ssm[];
    __nv_bfloat16* pIh = ssm;
    __nv_bfloat16* pIl = pIh + SIM_TILE;
    __nv_bfloat16* pJh = pIl + SIM_TILE;
    __nv_bfloat16* pJl = pJh + SIM_TILE;
    __nv_bfloat16* nJh = pJl + SIM_TILE;
    __nv_bfloat16* nJl = nJh + SIM_TILE;
    __shared__ float snI[128], snP[128], snN[128];
    __shared__ float rp[256], rn[256];

    int bi = blockIdx.y, bj = blockIdx.x, t = threadIdx.x;
    int wid = t >> 5, lane = t & 31;
    int wr = wid >> 1, wc = wid & 1;
    int g = lane >> 2, t4 = lane & 3;

    for (int i = t; i < 1024; i += 256) {
        int r = i >> 3, q = (i & 7) * 8;
        *(uint4*)(pIh + r * SIM_STR + q) = *(const uint4*)(g_pvh + (bi * 128 + r) * 64 + q);
        *(uint4*)(pIl + r * SIM_STR + q) = *(const uint4*)(g_pvl + (bi * 128 + r) * 64 + q);
        *(uint4*)(pJh + r * SIM_STR + q) = *(const uint4*)(g_pvh + (bj * 128 + r) * 64 + q);
        *(uint4*)(pJl + r * SIM_STR + q) = *(const uint4*)(g_pvl + (bj * 128 + r) * 64 + q);
        *(uint4*)(nJh + r * SIM_STR + q) = *(const uint4*)(g_nvh + (bj * 128 + r) * 64 + q);
        *(uint4*)(nJl + r * SIM_STR + q) = *(const uint4*)(g_nvl + (bj * 128 + r) * 64 + q);
    }
    if (t < 128) { snI[t] = g_psn[bi * 128 + t]; snN[t] = g_nsn[bj * 128 + t]; }
    else snP[t - 128] = g_psn[bj * 128 + (t - 128)];
    __syncthreads();

    float lp = 0.f, ln = 0.f;
#pragma unroll
    for (int targ = 0; targ < 2; targ++) {
        const __nv_bfloat16* Bh = targ ? nJh : pJh;
        const __nv_bfloat16* Bl = targ ? nJl : pJl;
        float acc[2][8][4];
#pragma unroll
        for (int r = 0; r < 2; r++)
#pragma unroll
            for (int c = 0; c < 8; c++)
#pragma unroll
                for (int j = 0; j < 4; j++) acc[r][c][j] = 0.f;

#pragma unroll
        for (int pass = 0; pass < 3; pass++) {
            const __nv_bfloat16* A = (pass == 2) ? pIl : pIh;
            const __nv_bfloat16* B = (pass == 1) ? Bl : Bh;
#pragma unroll
            for (int ks = 0; ks < 4; ks++) {
                int k0 = ks * 16;
                uint32_t af[2][4];
#pragma unroll
                for (int rt = 0; rt < 2; rt++) {
                    int row = wr * 32 + rt * 16;
                    af[rt][0] = *(const uint32_t*)(A + (row + g) * SIM_STR + k0 + 2 * t4);
                    af[rt][1] = *(const uint32_t*)(A + (row + g + 8) * SIM_STR + k0 + 2 * t4);
                    af[rt][2] = *(const uint32_t*)(A + (row + g) * SIM_STR + k0 + 2 * t4 + 8);
                    af[rt][3] = *(const uint32_t*)(A + (row + g + 8) * SIM_STR + k0 + 2 * t4 + 8);
                }
#pragma unroll
                for (int ct = 0; ct < 8; ct++) {
                    int n = wc * 64 + ct * 8;
                    uint32_t b0 = *(const uint32_t*)(B + (n + g) * SIM_STR + k0 + 2 * t4);
                    uint32_t b1 = *(const uint32_t*)(B + (n + g) * SIM_STR + k0 + 2 * t4 + 8);
                    mma_bf16(acc[0][ct], af[0], b0, b1);
                    mma_bf16(acc[1][ct], af[1], b0, b1);
                }
            }
        }

        const float* snX = targ ? snN : snP;
        float tot = 0.f;
#pragma unroll
        for (int rt = 0; rt < 2; rt++) {
#pragma unroll
            for (int ct = 0; ct < 8; ct++) {
                int rl = wr * 32 + rt * 16 + g;
                int cl = wc * 64 + ct * 8 + 2 * t4;
                float nI0 = snI[rl], nI1 = snI[rl + 8];
                float c0 = snX[cl], c1 = snX[cl + 1];
                float sqv[4] = { nI0 + c0 - 2.f * acc[rt][ct][0],
                                 nI0 + c1 - 2.f * acc[rt][ct][1],
                                 nI1 + c0 - 2.f * acc[rt][ct][2],
                                 nI1 + c1 - 2.f * acc[rt][ct][3] };
#pragma unroll
                for (int j = 0; j < 4; j++) {
                    float sq = fmaxf(sqv[j], 0.0f);
                    float d = (sq > 0.0f) ? sqrtf(sq) : 0.0f;
                    tot += __expf(-d);
                }
            }
        }
        if (targ == 0) lp = tot; else ln = tot;
    }
    rp[t] = lp; rn[t] = ln;
    __syncthreads();
    for (int o = 128; o; o >>= 1) {
        if (t < o) { rp[t] += rp[t + o]; rn[t] += rn[t + o]; }
        __syncthreads();
    }
    if (t == 0) {
        int bid = bi * 32 + bj;
        g_sp[bid] = rp[0]; g_sn[bid] = rn[0];
    }
}

__global__ void k_loss(float* __restrict__ out_loss) {
    __shared__ float rp[1024], rn[1024];
    int t = threadIdx.x;
    rp[t] = g_sp[t]; rn[t] = g_sn[t];
    __syncthreads();
    for (int o = 512; o; o >>= 1) {
        if (t < o) { rp[t] += rp[t + o]; rn[t] += rn[t + o]; }
        __syncthreads();
    }
    if (t == 0) out_loss[0] = -logf(rp[0] / rn[0]);
}

// ---------------- launch ----------------
extern "C" void kernel_launch(void* const* d_in, const int* in_sizes, int n_in,
                              void* d_out, int out_size) {
    const float* A     = (const float*)d_in[0];
    const int*   C     = (const int*)d_in[1];
    const float* L     = (const float*)d_in[2];
    const float* W1    = (const float*)d_in[3];
    const float* b1    = (const float*)d_in[4];
    const float* gam   = (const float*)d_in[5];
    const float* bet   = (const float*)d_in[6];
    const float* sig   = (const float*)d_in[7];
    const float* Pw    = (const float*)d_in[8];
    const float* Nw    = (const float*)d_in[9];
    const float* Wp1   = (const float*)d_in[10];
    const float* bp1   = (const float*)d_in[11];
    const float* Wp2   = (const float*)d_in[12];
    const float* bp2   = (const float*)d_in[13];
    const float* Wq1   = (const float*)d_in[14];
    const float* bq1   = (const float*)d_in[15];
    const float* Wq2   = (const float*)d_in[16];
    const float* bq2   = (const float*)d_in[17];
    const float* Wa    = (const float*)d_in[18];
    const float* ba    = (const float*)d_in[19];

    float* out = (float*)d_out;
    float* out_ff   = out;                    // [4096*64]
    float* out_loss = out + N_ * RED_;        // [1]
    float* out_D    = out + N_ * RED_ + 1;    // [4096*4096], only 4B-aligned!

    cudaFuncSetAttribute(k_gemm1_mma, cudaFuncAttributeMaxDynamicSharedMemorySize, G1_SMEM);
    cudaFuncSetAttribute(k_gemm2_mma, cudaFuncAttributeMaxDynamicSharedMemorySize, G2_SMEM);
    cudaFuncSetAttribute(k_sims_tc, cudaFuncAttributeMaxDynamicSharedMemorySize, SIMTC_SMEM);
    cudaFuncSetAttribute(k_dstats_tf32, cudaFuncAttributeMaxDynamicSharedMemorySize, DT_SMEM);

    k_wsplit<<<192, 256>>>(Wp1, Wq1, Wa, Wp2, Wq2);
    k_gather_h<<<N_, 128>>>(A, C, W1, b1);
    k_bnstats<<<1, 1024>>>();
    k_emb<<<512, 256>>>(gam, bet);
    k_dstats_tf32<<<dim3(32, 32), 256, DT_SMEM>>>(sig);
    k_dconsts<<<1, 1024>>>();
    k_dfinal<<<(N_ * (N_ / 4)) / 256, 256>>>(out_D);
    k_gemm1_mma<<<M1_ / 128, 512, G1_SMEM>>>(L, Pw, Nw, C, bp1, bq1, ba);
    k_gemm2_mma<<<M1_ / 128, 512, G2_SMEM>>>(bp2, bq2);
    k_r1<<<N_, 64>>>(out_ff);
    k_r2<<<N_, 128>>>();
    k_sims_tc<<<dim3(32, 32), 256, SIMTC_SMEM>>>();
    k_loss<<<1, 1024>>>(out_loss);
}